// round 9
// baseline (speedup 1.0000x reference)
#include <cuda_runtime.h>
#include <cuda_bf16.h>
#include <cstdint>

// Problem constants
#define BATCH   2
#define SEQ     2048
#define HEADS   16
#define DH      64
#define DIM     1024
#define INNER3  3072
#define NBLK    128
#define BLK     16
#define GK      1024        // K dim of both GEMMs

// Scratch (no allocations allowed -> device globals)
__device__ float g_qkv [(size_t)BATCH * SEQ * INNER3];  // [b*n, 3072]: q|k|v
__device__ __align__(16) __nv_bfloat16 g_a_hi [(size_t)BATCH * SEQ * DIM];   // split A (x, then attn)
__device__ __align__(16) __nv_bfloat16 g_a_lo [(size_t)BATCH * SEQ * DIM];
__device__ __align__(16) __nv_bfloat16 g_wq_hi[(size_t)INNER3 * DIM];        // w_qkv^T split [N,K]
__device__ __align__(16) __nv_bfloat16 g_wq_lo[(size_t)INNER3 * DIM];
__device__ __align__(16) __nv_bfloat16 g_wo_hi[(size_t)DIM * DIM];           // w_out^T split [N,K]
__device__ __align__(16) __nv_bfloat16 g_wo_lo[(size_t)DIM * DIM];

// ---------------------------------------------------------------------------
// Async-copy helpers
// ---------------------------------------------------------------------------
__device__ __forceinline__ uint32_t smem_u32(const void* p) {
    uint32_t a;
    asm("{ .reg .u64 t; cvta.to.shared.u64 t, %1; cvt.u32.u64 %0, t; }"
        : "=r"(a) : "l"(p));
    return a;
}
__device__ __forceinline__ void cp_async16(uint32_t dst, const void* src) {
    asm volatile("cp.async.cg.shared.global [%0], [%1], 16;" :: "r"(dst), "l"(src));
}
__device__ __forceinline__ void cp_commit() {
    asm volatile("cp.async.commit_group;");
}
__device__ __forceinline__ void cp_wait0() {
    asm volatile("cp.async.wait_group 0;" ::: "memory");
}
__device__ __forceinline__ void mma_bf16(float c[4], uint32_t a0, uint32_t a1,
                                         uint32_t a2, uint32_t a3,
                                         uint32_t b0, uint32_t b1) {
    asm volatile(
        "mma.sync.aligned.m16n8k16.row.col.f32.bf16.bf16.f32 "
        "{%0,%1,%2,%3}, {%4,%5,%6,%7}, {%8,%9}, {%0,%1,%2,%3};"
        : "+f"(c[0]), "+f"(c[1]), "+f"(c[2]), "+f"(c[3])
        : "r"(a0), "r"(a1), "r"(a2), "r"(a3), "r"(b0), "r"(b1));
}

// ---------------------------------------------------------------------------
// HMMA bf16-split GEMM (unchanged from the passing round-8 kernel).
// C[M,Ntot] = A[M,GK] @ Bt[Ntot,GK]^T (+bias)
// CTA tile 128x128, BK=32, 256 threads = 8 warps in 2(m) x 4(n), warp tile 64x32.
// 3-way split per k16 step: AhBh + AhBl + AlBh (drops AlBl, ~2^-16 relative).
// ---------------------------------------------------------------------------
#define BK      32
#define ROWP    40                         // padded row length in bf16
#define ARR_B   (128 * ROWP * 2)           // 10240 bytes per array
#define STG_B   (4 * ARR_B)                // 40960 bytes per stage
#define SM_GEMM (2 * STG_B)                // 81920

template <bool HAS_BIAS>
__device__ __forceinline__ void hmma_gemm_body(
    const __nv_bfloat16* __restrict__ Ahi, const __nv_bfloat16* __restrict__ Alo,
    const __nv_bfloat16* __restrict__ Bhi, const __nv_bfloat16* __restrict__ Blo,
    const float* __restrict__ bias, float* __restrict__ C, int Ntot)
{
    extern __shared__ char dsm[];
    const uint32_t smb = smem_u32(dsm);

    const int t    = threadIdx.x;          // 0..255
    const int lane = t & 31;
    const int wid  = t >> 5;               // 0..7
    const int wm   = wid >> 2;             // 0..1
    const int wn   = wid & 3;              // 0..3
    const int gid  = lane >> 2;            // 0..7
    const int tg   = lane & 3;             // 0..3
    const int bn0  = blockIdx.x * 128;
    const int bm0  = blockIdx.y * 128;

    float acc[4][4][4];
    #pragma unroll
    for (int i = 0; i < 4; i++)
        #pragma unroll
        for (int j = 0; j < 4; j++)
            #pragma unroll
            for (int k = 0; k < 4; k++) acc[i][j][k] = 0.f;

    const __nv_bfloat16* gA[2] = { Ahi + (size_t)bm0 * GK, Alo + (size_t)bm0 * GK };
    const __nv_bfloat16* gB[2] = { Bhi + (size_t)bn0 * GK, Blo + (size_t)bn0 * GK };

    auto load_stage = [&](int stage, int kofs) {
        const uint32_t base = smb + stage * STG_B;
        #pragma unroll
        for (int arr = 0; arr < 4; arr++) {          // 0:Ah 1:Al 2:Bh 3:Bl
            const __nv_bfloat16* src = (arr < 2) ? gA[arr] : gB[arr - 2];
            const uint32_t dst0 = base + arr * ARR_B;
            #pragma unroll
            for (int i = 0; i < 2; i++) {
                int idx = t + i * 256;               // 0..511
                int row = idx >> 2;                  // 0..127
                int c16 = idx & 3;                   // 0..3
                cp_async16(dst0 + row * (ROWP * 2) + c16 * 16,
                           src + (size_t)row * GK + kofs + c16 * 8);
            }
        }
        cp_commit();
    };

    load_stage(0, 0);
    cp_wait0();
    __syncthreads();

    int cur = 0;
    for (int kc = 0; kc < GK / BK; kc++) {
        const int nxt = cur ^ 1;
        if (kc + 1 < GK / BK) load_stage(nxt, (kc + 1) * BK);

        const uint32_t* Ah = (const uint32_t*)(dsm + cur * STG_B + 0 * ARR_B);
        const uint32_t* Al = (const uint32_t*)(dsm + cur * STG_B + 1 * ARR_B);
        const uint32_t* Bh = (const uint32_t*)(dsm + cur * STG_B + 2 * ARR_B);
        const uint32_t* Bl = (const uint32_t*)(dsm + cur * STG_B + 3 * ARR_B);

        #pragma unroll
        for (int ks = 0; ks < 2; ks++) {             // two k16 steps per BK=32
            const int ko = ks * 8 + tg;              // u32 column offset
            uint32_t ah[4][4], al[4][4], bh[4][2], bl[4][2];
            #pragma unroll
            for (int mf = 0; mf < 4; mf++) {
                int rb = (wm * 64 + mf * 16 + gid) * (ROWP / 2) + ko;
                ah[mf][0] = Ah[rb];
                ah[mf][1] = Ah[rb + 8 * (ROWP / 2)];
                ah[mf][2] = Ah[rb + 4];
                ah[mf][3] = Ah[rb + 8 * (ROWP / 2) + 4];
                al[mf][0] = Al[rb];
                al[mf][1] = Al[rb + 8 * (ROWP / 2)];
                al[mf][2] = Al[rb + 4];
                al[mf][3] = Al[rb + 8 * (ROWP / 2) + 4];
            }
            #pragma unroll
            for (int nf = 0; nf < 4; nf++) {
                int nb = (wn * 32 + nf * 8 + gid) * (ROWP / 2) + ko;
                bh[nf][0] = Bh[nb];
                bh[nf][1] = Bh[nb + 4];
                bl[nf][0] = Bl[nb];
                bl[nf][1] = Bl[nb + 4];
            }
            #pragma unroll
            for (int mf = 0; mf < 4; mf++)
                #pragma unroll
                for (int nf = 0; nf < 4; nf++) {
                    mma_bf16(acc[mf][nf], ah[mf][0], ah[mf][1], ah[mf][2], ah[mf][3],
                             bh[nf][0], bh[nf][1]);
                    mma_bf16(acc[mf][nf], ah[mf][0], ah[mf][1], ah[mf][2], ah[mf][3],
                             bl[nf][0], bl[nf][1]);
                    mma_bf16(acc[mf][nf], al[mf][0], al[mf][1], al[mf][2], al[mf][3],
                             bh[nf][0], bh[nf][1]);
                }
        }

        cp_wait0();
        __syncthreads();
        cur = nxt;
    }

    #pragma unroll
    for (int mf = 0; mf < 4; mf++) {
        int row = bm0 + wm * 64 + mf * 16 + gid;
        #pragma unroll
        for (int nf = 0; nf < 4; nf++) {
            int col = bn0 + wn * 32 + nf * 8 + tg * 2;
            float bx = 0.f, by = 0.f;
            if (HAS_BIAS) { bx = bias[col]; by = bias[col + 1]; }
            float2 v0 = make_float2(acc[mf][nf][0] + bx, acc[mf][nf][1] + by);
            float2 v1 = make_float2(acc[mf][nf][2] + bx, acc[mf][nf][3] + by);
            *(float2*)(C + (size_t)row * Ntot + col)       = v0;
            *(float2*)(C + (size_t)(row + 8) * Ntot + col) = v1;
        }
    }
}

__global__ __launch_bounds__(256) void tc_gemm1_kernel()
{
    hmma_gemm_body<false>(g_a_hi, g_a_lo, g_wq_hi, g_wq_lo, nullptr, g_qkv, INNER3);
}

__global__ __launch_bounds__(256) void tc_gemm2_kernel(const float* __restrict__ bias,
                                                       float* __restrict__ out)
{
    hmma_gemm_body<true>(g_a_hi, g_a_lo, g_wo_hi, g_wo_lo, bias, out, DIM);
}

// ---------------------------------------------------------------------------
// fp32 -> (bf16 hi, bf16 lo) elementwise split for x. 4 elems/thread.
// ---------------------------------------------------------------------------
__global__ __launch_bounds__(256) void split_x_kernel(const float* __restrict__ x)
{
    const int i0 = (blockIdx.x * 256 + threadIdx.x) * 4;
    float4 v = *(const float4*)(x + i0);
    __nv_bfloat16 h0 = __float2bfloat16(v.x);
    __nv_bfloat16 h1 = __float2bfloat16(v.y);
    __nv_bfloat16 h2 = __float2bfloat16(v.z);
    __nv_bfloat16 h3 = __float2bfloat16(v.w);
    __nv_bfloat16 l0 = __float2bfloat16(v.x - __bfloat162float(h0));
    __nv_bfloat16 l1 = __float2bfloat16(v.y - __bfloat162float(h1));
    __nv_bfloat16 l2 = __float2bfloat16(v.z - __bfloat162float(h2));
    __nv_bfloat16 l3 = __float2bfloat16(v.w - __bfloat162float(h3));
    __nv_bfloat162 hh0; hh0.x = h0; hh0.y = h1;
    __nv_bfloat162 hh1; hh1.x = h2; hh1.y = h3;
    __nv_bfloat162 ll0; ll0.x = l0; ll0.y = l1;
    __nv_bfloat162 ll1; ll1.x = l2; ll1.y = l3;
    *(__nv_bfloat162*)(g_a_hi + i0)     = hh0;
    *(__nv_bfloat162*)(g_a_hi + i0 + 2) = hh1;
    *(__nv_bfloat162*)(g_a_lo + i0)     = ll0;
    *(__nv_bfloat162*)(g_a_lo + i0 + 2) = ll1;
}

// ---------------------------------------------------------------------------
// Transpose + split: src [GK x N] fp32 -> dst_hi/lo [N x GK] bf16
// ---------------------------------------------------------------------------
__device__ __forceinline__ void tsp_body(const float* __restrict__ src,
                                         __nv_bfloat16* __restrict__ dhi,
                                         __nv_bfloat16* __restrict__ dlo, int N)
{
    __shared__ float tile[32][33];
    const int bx = blockIdx.x * 32;   // N offset
    const int by = blockIdx.y * 32;   // K offset
    const int tx = threadIdx.x & 31;
    const int ty = threadIdx.x >> 5;  // 0..7
    #pragma unroll
    for (int i = 0; i < 4; i++)
        tile[ty + i * 8][tx] = src[(size_t)(by + ty + i * 8) * N + bx + tx];
    __syncthreads();
    #pragma unroll
    for (int i = 0; i < 4; i++) {
        float v = tile[tx][ty + i * 8];
        __nv_bfloat16 h = __float2bfloat16(v);
        __nv_bfloat16 l = __float2bfloat16(v - __bfloat162float(h));
        size_t o = (size_t)(bx + ty + i * 8) * GK + by + tx;
        dhi[o] = h;
        dlo[o] = l;
    }
}

__global__ __launch_bounds__(256) void tsp_wq_kernel(const float* __restrict__ w)
{
    tsp_body(w, g_wq_hi, g_wq_lo, INNER3);
}
__global__ __launch_bounds__(256) void tsp_wo_kernel(const float* __restrict__ w)
{
    tsp_body(w, g_wo_hi, g_wo_lo, DIM);
}

// ---------------------------------------------------------------------------
// Block-sparse causal attention.
// grid = (NBLK, HEADS, BATCH), 128 threads, 3 CTAs/SM.
// Thread t: c = t&15 (key col), rp = t>>4 -> rows {2rp, 2rp+1}.
// Q rows held in REGISTERS (loaded once) -> score-phase LDS drops 48->16
// float4/thread/iter. Epilogue writes bf16 hi/lo split directly (gemm2 input).
// ---------------------------------------------------------------------------
#define SP 68   // smem row stride in floats: 272B, 16B-aligned, 2-way max conflict

__global__ __launch_bounds__(128, 3) void sparse_attn_kernel(const void* __restrict__ layout_raw)
{
    const int qb = blockIdx.x;
    const int h  = blockIdx.y;
    const int b  = blockIdx.z;

    const int t  = threadIdx.x;       // 0..127
    const int c  = t & 15;
    const int rp = t >> 4;            // 0..7
    const int r0 = rp * 2;
    const int r1 = rp * 2 + 1;
    const int c0 = c * 4;
    const int lanebase = t & 16;      // bit 4 of lane id within warp

    __shared__ float qs[16 * SP];
    __shared__ float ks[16 * SP];
    __shared__ float vs[16 * SP];

    // Layout dtype auto-detect: layout[1][0] is deterministically True
    // (global column 0 survives tril). byte 128 == 1 iff buffer is bool/uint8.
    const unsigned char* lb = (const unsigned char*)layout_raw;
    const bool is_u8 = (lb[128] != 0);
    const uint32_t* lw = (const uint32_t*)layout_raw;

    const float* base = g_qkv + (size_t)b * SEQ * INNER3;

    // Stage Q tile through smem (coalesced), then hoist this thread's two
    // rows into registers for the whole jb loop.
    #pragma unroll
    for (int it = 0; it < 2; it++) {
        int f = t + it * 128;
        int row = f >> 4, cc = f & 15;
        float4 v = *(const float4*)(base + (size_t)(qb * BLK + row) * INNER3 + h * DH + cc * 4);
        *(float4*)(qs + row * SP + cc * 4) = v;
    }
    __syncthreads();

    float4 q0r[16], q1r[16];
    {
        const float4* q0 = (const float4*)(qs + r0 * SP);
        const float4* q1 = (const float4*)(qs + r1 * SP);
        #pragma unroll
        for (int d = 0; d < 16; d++) { q0r[d] = q0[d]; q1r[d] = q1[d]; }
    }

    float m0 = -1e30f, l0 = 0.f, m1 = -1e30f, l1 = 0.f;
    float4 o0 = make_float4(0.f, 0.f, 0.f, 0.f);
    float4 o1 = make_float4(0.f, 0.f, 0.f, 0.f);
    const float scale = 0.125f;   // 1/sqrt(64)

    for (int jb = 0; jb <= qb; jb++) {
        bool allowed = is_u8 ? (lb[qb * NBLK + jb] != 0)
                             : (lw[qb * NBLK + jb] != 0u);
        if (!allowed) continue;

        __syncthreads();   // previous iteration done reading ks/vs

        // Load K and V tiles [16,64] each
        #pragma unroll
        for (int it = 0; it < 2; it++) {
            int f = t + it * 128;
            int row = f >> 4, cc = f & 15;
            const float* rowp = base + (size_t)(jb * BLK + row) * INNER3 + h * DH + cc * 4;
            *(float4*)(ks + row * SP + cc * 4) = *(const float4*)(rowp + DIM);
            *(float4*)(vs + row * SP + cc * 4) = *(const float4*)(rowp + 2 * DIM);
        }
        __syncthreads();

        // Scores: thread computes S[r0][c], S[r1][c]; K column read once,
        // Q comes from registers (no LDS).
        float s0 = 0.f, s1 = 0.f;
        {
            const float4* kp = (const float4*)(ks + c * SP);
            #pragma unroll
            for (int d = 0; d < 16; d++) {
                float4 kk = kp[d];
                s0 += q0r[d].x * kk.x + q0r[d].y * kk.y + q0r[d].z * kk.z + q0r[d].w * kk.w;
                s1 += q1r[d].x * kk.x + q1r[d].y * kk.y + q1r[d].z * kk.z + q1r[d].w * kk.w;
            }
        }
        s0 *= scale;
        s1 *= scale;
        if (jb == qb) {                     // causal within diagonal block
            if (c > r0) s0 = -1e30f;
            if (c > r1) s1 = -1e30f;
        }

        // Row max over the 16-lane column group
        float mr0 = s0, mr1 = s1;
        #pragma unroll
        for (int k = 1; k < 16; k <<= 1) {
            mr0 = fmaxf(mr0, __shfl_xor_sync(0xffffffffu, mr0, k, 32));
            mr1 = fmaxf(mr1, __shfl_xor_sync(0xffffffffu, mr1, k, 32));
        }
        float mn0 = fmaxf(m0, mr0);
        float mn1 = fmaxf(m1, mr1);
        float p0  = __expf(s0 - mn0);
        float p1  = __expf(s1 - mn1);
        float cr0 = __expf(m0 - mn0);
        float cr1 = __expf(m1 - mn1);

        // Row sum
        float sm0 = p0, sm1 = p1;
        #pragma unroll
        for (int k = 1; k < 16; k <<= 1) {
            sm0 += __shfl_xor_sync(0xffffffffu, sm0, k, 32);
            sm1 += __shfl_xor_sync(0xffffffffu, sm1, k, 32);
        }
        l0 = l0 * cr0 + sm0;  m0 = mn0;
        l1 = l1 * cr1 + sm1;  m1 = mn1;
        o0.x *= cr0; o0.y *= cr0; o0.z *= cr0; o0.w *= cr0;
        o1.x *= cr1; o1.y *= cr1; o1.z *= cr1; o1.w *= cr1;

        // O[r][c0..c0+3] += P[r][:] @ V[:, c0..c0+3]; P broadcast via shuffle.
        #pragma unroll
        for (int j = 0; j < 16; j++) {
            float pj0 = __shfl_sync(0xffffffffu, p0, lanebase | j, 32);
            float pj1 = __shfl_sync(0xffffffffu, p1, lanebase | j, 32);
            float4 vv = *(const float4*)(vs + j * SP + c0);
            o0.x += pj0 * vv.x; o0.y += pj0 * vv.y; o0.z += pj0 * vv.z; o0.w += pj0 * vv.w;
            o1.x += pj1 * vv.x; o1.y += pj1 * vv.y; o1.z += pj1 * vv.z; o1.w += pj1 * vv.w;
        }
    }

    // Epilogue: normalize and write bf16 hi/lo split directly (gemm2 input).
    const float inv0 = 1.f / l0;
    const float inv1 = 1.f / l1;
    const size_t ob0 = (size_t)(b * SEQ + qb * BLK + r0) * DIM + h * DH + c0;
    const size_t ob1 = (size_t)(b * SEQ + qb * BLK + r1) * DIM + h * DH + c0;

    float v0[4] = { o0.x * inv0, o0.y * inv0, o0.z * inv0, o0.w * inv0 };
    float v1[4] = { o1.x * inv1, o1.y * inv1, o1.z * inv1, o1.w * inv1 };

    __nv_bfloat162 h0a, h0b, l0a, l0b, h1a, h1b, l1a, l1b;
    h0a.x = __float2bfloat16(v0[0]); h0a.y = __float2bfloat16(v0[1]);
    h0b.x = __float2bfloat16(v0[2]); h0b.y = __float2bfloat16(v0[3]);
    l0a.x = __float2bfloat16(v0[0] - __bfloat162float(h0a.x));
    l0a.y = __float2bfloat16(v0[1] - __bfloat162float(h0a.y));
    l0b.x = __float2bfloat16(v0[2] - __bfloat162float(h0b.x));
    l0b.y = __float2bfloat16(v0[3] - __bfloat162float(h0b.y));
    h1a.x = __float2bfloat16(v1[0]); h1a.y = __float2bfloat16(v1[1]);
    h1b.x = __float2bfloat16(v1[2]); h1b.y = __float2bfloat16(v1[3]);
    l1a.x = __float2bfloat16(v1[0] - __bfloat162float(h1a.x));
    l1a.y = __float2bfloat16(v1[1] - __bfloat162float(h1a.y));
    l1b.x = __float2bfloat16(v1[2] - __bfloat162float(h1b.x));
    l1b.y = __float2bfloat16(v1[3] - __bfloat162float(h1b.y));

    *(__nv_bfloat162*)(g_a_hi + ob0)     = h0a;
    *(__nv_bfloat162*)(g_a_hi + ob0 + 2) = h0b;
    *(__nv_bfloat162*)(g_a_lo + ob0)     = l0a;
    *(__nv_bfloat162*)(g_a_lo + ob0 + 2) = l0b;
    *(__nv_bfloat162*)(g_a_hi + ob1)     = h1a;
    *(__nv_bfloat162*)(g_a_hi + ob1 + 2) = h1b;
    *(__nv_bfloat162*)(g_a_lo + ob1)     = l1a;
    *(__nv_bfloat162*)(g_a_lo + ob1 + 2) = l1b;
}

// ---------------------------------------------------------------------------
// Inputs: 0:x [2,2048,1024] f32  1:w_qkv [1024,3072] f32
//         2:w_out [1024,1024] f32  3:b_out [1024] f32  4:layout [128,128] bool
// Output: [2,2048,1024] f32
// ---------------------------------------------------------------------------
extern "C" void kernel_launch(void* const* d_in, const int* in_sizes, int n_in,
                              void* d_out, int out_size)
{
    const float* x      = (const float*)d_in[0];
    const float* w_qkv  = (const float*)d_in[1];
    const float* w_out  = (const float*)d_in[2];
    const float* b_out  = (const float*)d_in[3];
    const void*  layout = d_in[4];
    float* out = (float*)d_out;

    cudaFuncSetAttribute(tc_gemm1_kernel,
                         cudaFuncAttributeMaxDynamicSharedMemorySize, SM_GEMM);
    cudaFuncSetAttribute(tc_gemm2_kernel,
                         cudaFuncAttributeMaxDynamicSharedMemorySize, SM_GEMM);

    // Prep: weight transposes + splits, x split
    {
        dim3 g1(INNER3 / 32, GK / 32);
        tsp_wq_kernel<<<g1, 256>>>(w_qkv);
        dim3 g2(DIM / 32, GK / 32);
        tsp_wo_kernel<<<g2, 256>>>(w_out);
        split_x_kernel<<<(BATCH * SEQ * DIM) / (256 * 4), 256>>>(x);
    }
    // 1) QKV projection (HMMA bf16-split): [4096,1024] @ [1024,3072] -> g_qkv
    {
        dim3 grid(INNER3 / 128, (BATCH * SEQ) / 128);
        tc_gemm1_kernel<<<grid, 256, SM_GEMM>>>();
    }
    // 2) Block-sparse causal attention -> g_a_hi/g_a_lo (bf16 split, fused)
    {
        dim3 grid(NBLK, HEADS, BATCH);
        sparse_attn_kernel<<<grid, 128>>>(layout);
    }
    // 3) Output projection (HMMA) + bias -> out
    {
        dim3 grid(DIM / 128, (BATCH * SEQ) / 128);
        tc_gemm2_kernel<<<grid, 256, SM_GEMM>>>(b_out, out);
    }
}

// round 10
// speedup vs baseline: 1.0712x; 1.0712x over previous
#include <cuda_runtime.h>
#include <cuda_bf16.h>
#include <cstdint>

// Problem constants
#define BATCH   2
#define SEQ     2048
#define HEADS   16
#define DH      64
#define DIM     1024
#define INNER3  3072
#define NBLK    128
#define BLK     16
#define GK      1024        // K dim of both GEMMs

// Scratch (no allocations allowed -> device globals)
__device__ float g_qkv [(size_t)BATCH * SEQ * INNER3];  // [b*n, 3072]: q|k|v
__device__ __align__(16) __nv_bfloat16 g_a_hi [(size_t)BATCH * SEQ * DIM];   // split A (x, then attn)
__device__ __align__(16) __nv_bfloat16 g_a_lo [(size_t)BATCH * SEQ * DIM];
__device__ __align__(16) __nv_bfloat16 g_wq_hi[(size_t)INNER3 * DIM];        // w_qkv^T split [N,K]
__device__ __align__(16) __nv_bfloat16 g_wq_lo[(size_t)INNER3 * DIM];
__device__ __align__(16) __nv_bfloat16 g_wo_hi[(size_t)DIM * DIM];           // w_out^T split [N,K]
__device__ __align__(16) __nv_bfloat16 g_wo_lo[(size_t)DIM * DIM];

// ---------------------------------------------------------------------------
// Async-copy helpers
// ---------------------------------------------------------------------------
__device__ __forceinline__ uint32_t smem_u32(const void* p) {
    uint32_t a;
    asm("{ .reg .u64 t; cvta.to.shared.u64 t, %1; cvt.u32.u64 %0, t; }"
        : "=r"(a) : "l"(p));
    return a;
}
__device__ __forceinline__ void cp_async16(uint32_t dst, const void* src) {
    asm volatile("cp.async.cg.shared.global [%0], [%1], 16;" :: "r"(dst), "l"(src));
}
__device__ __forceinline__ void cp_commit() {
    asm volatile("cp.async.commit_group;");
}
__device__ __forceinline__ void cp_wait0() {
    asm volatile("cp.async.wait_group 0;" ::: "memory");
}
__device__ __forceinline__ void cp_wait1() {
    asm volatile("cp.async.wait_group 1;" ::: "memory");
}
__device__ __forceinline__ void mma_bf16(float c[4], uint32_t a0, uint32_t a1,
                                         uint32_t a2, uint32_t a3,
                                         uint32_t b0, uint32_t b1) {
    asm volatile(
        "mma.sync.aligned.m16n8k16.row.col.f32.bf16.bf16.f32 "
        "{%0,%1,%2,%3}, {%4,%5,%6,%7}, {%8,%9}, {%0,%1,%2,%3};"
        : "+f"(c[0]), "+f"(c[1]), "+f"(c[2]), "+f"(c[3])
        : "r"(a0), "r"(a1), "r"(a2), "r"(a3), "r"(b0), "r"(b1));
}

// ---------------------------------------------------------------------------
// HMMA bf16-split GEMM (unchanged from the passing round-8 kernel).
// ---------------------------------------------------------------------------
#define BK      32
#define ROWP    40                         // padded row length in bf16
#define ARR_B   (128 * ROWP * 2)           // 10240 bytes per array
#define STG_B   (4 * ARR_B)                // 40960 bytes per stage
#define SM_GEMM (2 * STG_B)                // 81920

template <bool HAS_BIAS>
__device__ __forceinline__ void hmma_gemm_body(
    const __nv_bfloat16* __restrict__ Ahi, const __nv_bfloat16* __restrict__ Alo,
    const __nv_bfloat16* __restrict__ Bhi, const __nv_bfloat16* __restrict__ Blo,
    const float* __restrict__ bias, float* __restrict__ C, int Ntot)
{
    extern __shared__ char dsm[];
    const uint32_t smb = smem_u32(dsm);

    const int t    = threadIdx.x;          // 0..255
    const int lane = t & 31;
    const int wid  = t >> 5;               // 0..7
    const int wm   = wid >> 2;             // 0..1
    const int wn   = wid & 3;              // 0..3
    const int gid  = lane >> 2;            // 0..7
    const int tg   = lane & 3;             // 0..3
    const int bn0  = blockIdx.x * 128;
    const int bm0  = blockIdx.y * 128;

    float acc[4][4][4];
    #pragma unroll
    for (int i = 0; i < 4; i++)
        #pragma unroll
        for (int j = 0; j < 4; j++)
            #pragma unroll
            for (int k = 0; k < 4; k++) acc[i][j][k] = 0.f;

    const __nv_bfloat16* gA[2] = { Ahi + (size_t)bm0 * GK, Alo + (size_t)bm0 * GK };
    const __nv_bfloat16* gB[2] = { Bhi + (size_t)bn0 * GK, Blo + (size_t)bn0 * GK };

    auto load_stage = [&](int stage, int kofs) {
        const uint32_t base = smb + stage * STG_B;
        #pragma unroll
        for (int arr = 0; arr < 4; arr++) {          // 0:Ah 1:Al 2:Bh 3:Bl
            const __nv_bfloat16* src = (arr < 2) ? gA[arr] : gB[arr - 2];
            const uint32_t dst0 = base + arr * ARR_B;
            #pragma unroll
            for (int i = 0; i < 2; i++) {
                int idx = t + i * 256;               // 0..511
                int row = idx >> 2;                  // 0..127
                int c16 = idx & 3;                   // 0..3
                cp_async16(dst0 + row * (ROWP * 2) + c16 * 16,
                           src + (size_t)row * GK + kofs + c16 * 8);
            }
        }
        cp_commit();
    };

    load_stage(0, 0);
    cp_wait0();
    __syncthreads();

    int cur = 0;
    for (int kc = 0; kc < GK / BK; kc++) {
        const int nxt = cur ^ 1;
        if (kc + 1 < GK / BK) load_stage(nxt, (kc + 1) * BK);

        const uint32_t* Ah = (const uint32_t*)(dsm + cur * STG_B + 0 * ARR_B);
        const uint32_t* Al = (const uint32_t*)(dsm + cur * STG_B + 1 * ARR_B);
        const uint32_t* Bh = (const uint32_t*)(dsm + cur * STG_B + 2 * ARR_B);
        const uint32_t* Bl = (const uint32_t*)(dsm + cur * STG_B + 3 * ARR_B);

        #pragma unroll
        for (int ks = 0; ks < 2; ks++) {             // two k16 steps per BK=32
            const int ko = ks * 8 + tg;              // u32 column offset
            uint32_t ah[4][4], al[4][4], bh[4][2], bl[4][2];
            #pragma unroll
            for (int mf = 0; mf < 4; mf++) {
                int rb = (wm * 64 + mf * 16 + gid) * (ROWP / 2) + ko;
                ah[mf][0] = Ah[rb];
                ah[mf][1] = Ah[rb + 8 * (ROWP / 2)];
                ah[mf][2] = Ah[rb + 4];
                ah[mf][3] = Ah[rb + 8 * (ROWP / 2) + 4];
                al[mf][0] = Al[rb];
                al[mf][1] = Al[rb + 8 * (ROWP / 2)];
                al[mf][2] = Al[rb + 4];
                al[mf][3] = Al[rb + 8 * (ROWP / 2) + 4];
            }
            #pragma unroll
            for (int nf = 0; nf < 4; nf++) {
                int nb = (wn * 32 + nf * 8 + gid) * (ROWP / 2) + ko;
                bh[nf][0] = Bh[nb];
                bh[nf][1] = Bh[nb + 4];
                bl[nf][0] = Bl[nb];
                bl[nf][1] = Bl[nb + 4];
            }
            #pragma unroll
            for (int mf = 0; mf < 4; mf++)
                #pragma unroll
                for (int nf = 0; nf < 4; nf++) {
                    mma_bf16(acc[mf][nf], ah[mf][0], ah[mf][1], ah[mf][2], ah[mf][3],
                             bh[nf][0], bh[nf][1]);
                    mma_bf16(acc[mf][nf], ah[mf][0], ah[mf][1], ah[mf][2], ah[mf][3],
                             bl[nf][0], bl[nf][1]);
                    mma_bf16(acc[mf][nf], al[mf][0], al[mf][1], al[mf][2], al[mf][3],
                             bh[nf][0], bh[nf][1]);
                }
        }

        cp_wait0();
        __syncthreads();
        cur = nxt;
    }

    #pragma unroll
    for (int mf = 0; mf < 4; mf++) {
        int row = bm0 + wm * 64 + mf * 16 + gid;
        #pragma unroll
        for (int nf = 0; nf < 4; nf++) {
            int col = bn0 + wn * 32 + nf * 8 + tg * 2;
            float bx = 0.f, by = 0.f;
            if (HAS_BIAS) { bx = bias[col]; by = bias[col + 1]; }
            float2 v0 = make_float2(acc[mf][nf][0] + bx, acc[mf][nf][1] + by);
            float2 v1 = make_float2(acc[mf][nf][2] + bx, acc[mf][nf][3] + by);
            *(float2*)(C + (size_t)row * Ntot + col)       = v0;
            *(float2*)(C + (size_t)(row + 8) * Ntot + col) = v1;
        }
    }
}

__global__ __launch_bounds__(256) void tc_gemm1_kernel()
{
    hmma_gemm_body<false>(g_a_hi, g_a_lo, g_wq_hi, g_wq_lo, nullptr, g_qkv, INNER3);
}

__global__ __launch_bounds__(256) void tc_gemm2_kernel(const float* __restrict__ bias,
                                                       float* __restrict__ out)
{
    hmma_gemm_body<true>(g_a_hi, g_a_lo, g_wo_hi, g_wo_lo, bias, out, DIM);
}

// ---------------------------------------------------------------------------
// fp32 -> (bf16 hi, bf16 lo) elementwise split for x. 4 elems/thread.
// ---------------------------------------------------------------------------
__global__ __launch_bounds__(256) void split_x_kernel(const float* __restrict__ x)
{
    const int i0 = (blockIdx.x * 256 + threadIdx.x) * 4;
    float4 v = *(const float4*)(x + i0);
    __nv_bfloat16 h0 = __float2bfloat16(v.x);
    __nv_bfloat16 h1 = __float2bfloat16(v.y);
    __nv_bfloat16 h2 = __float2bfloat16(v.z);
    __nv_bfloat16 h3 = __float2bfloat16(v.w);
    __nv_bfloat16 l0 = __float2bfloat16(v.x - __bfloat162float(h0));
    __nv_bfloat16 l1 = __float2bfloat16(v.y - __bfloat162float(h1));
    __nv_bfloat16 l2 = __float2bfloat16(v.z - __bfloat162float(h2));
    __nv_bfloat16 l3 = __float2bfloat16(v.w - __bfloat162float(h3));
    __nv_bfloat162 hh0; hh0.x = h0; hh0.y = h1;
    __nv_bfloat162 hh1; hh1.x = h2; hh1.y = h3;
    __nv_bfloat162 ll0; ll0.x = l0; ll0.y = l1;
    __nv_bfloat162 ll1; ll1.x = l2; ll1.y = l3;
    *(__nv_bfloat162*)(g_a_hi + i0)     = hh0;
    *(__nv_bfloat162*)(g_a_hi + i0 + 2) = hh1;
    *(__nv_bfloat162*)(g_a_lo + i0)     = ll0;
    *(__nv_bfloat162*)(g_a_lo + i0 + 2) = ll1;
}

// ---------------------------------------------------------------------------
// Transpose + split: src [GK x N] fp32 -> dst_hi/lo [N x GK] bf16
// ---------------------------------------------------------------------------
__device__ __forceinline__ void tsp_body(const float* __restrict__ src,
                                         __nv_bfloat16* __restrict__ dhi,
                                         __nv_bfloat16* __restrict__ dlo, int N)
{
    __shared__ float tile[32][33];
    const int bx = blockIdx.x * 32;   // N offset
    const int by = blockIdx.y * 32;   // K offset
    const int tx = threadIdx.x & 31;
    const int ty = threadIdx.x >> 5;  // 0..7
    #pragma unroll
    for (int i = 0; i < 4; i++)
        tile[ty + i * 8][tx] = src[(size_t)(by + ty + i * 8) * N + bx + tx];
    __syncthreads();
    #pragma unroll
    for (int i = 0; i < 4; i++) {
        float v = tile[tx][ty + i * 8];
        __nv_bfloat16 h = __float2bfloat16(v);
        __nv_bfloat16 l = __float2bfloat16(v - __bfloat162float(h));
        size_t o = (size_t)(bx + ty + i * 8) * GK + by + tx;
        dhi[o] = h;
        dlo[o] = l;
    }
}

__global__ __launch_bounds__(256) void tsp_wq_kernel(const float* __restrict__ w)
{
    tsp_body(w, g_wq_hi, g_wq_lo, INNER3);
}
__global__ __launch_bounds__(256) void tsp_wo_kernel(const float* __restrict__ w)
{
    tsp_body(w, g_wo_hi, g_wo_lo, DIM);
}

// ---------------------------------------------------------------------------
// Block-sparse causal attention, cp.async double-buffered.
// grid = (NBLK, HEADS, BATCH), 128 threads.
// Allowed-jb list built via ballot (thread t <-> jb t). K/V tiles for block
// i+1 prefetched via cp.async while block i computes -> global latency hidden.
// Q read from smem (round-8 layout; register hoist reverted — it regressed).
// Epilogue writes the bf16 hi/lo split directly (gemm2 input).
// ---------------------------------------------------------------------------
#define SP 68   // smem row stride in floats: 272B, 16B-aligned, 2-way max conflict

__global__ __launch_bounds__(128) void sparse_attn_kernel(const void* __restrict__ layout_raw)
{
    const int qb = blockIdx.x;
    const int h  = blockIdx.y;
    const int b  = blockIdx.z;

    const int t    = threadIdx.x;     // 0..127
    const int c    = t & 15;
    const int rp   = t >> 4;          // 0..7
    const int r0   = rp * 2;
    const int r1   = rp * 2 + 1;
    const int c0   = c * 4;
    const int lanebase = t & 16;
    const int warp = t >> 5;
    const int lane = t & 31;

    __shared__ float    qs[16 * SP];
    __shared__ float    ks[2][16 * SP];
    __shared__ float    vs[2][16 * SP];
    __shared__ int      jlist[NBLK];
    __shared__ uint32_t wmask[4];

    // Layout dtype auto-detect: layout[1][0] is deterministically True
    // (global column 0 survives tril). byte 128 == 1 iff buffer is bool/uint8.
    const unsigned char* lb = (const unsigned char*)layout_raw;
    const bool is_u8 = (lb[128] != 0);
    const uint32_t* lw = (const uint32_t*)layout_raw;

    const float* base = g_qkv + (size_t)b * SEQ * INNER3;

    // Ballot pass: thread t checks jb = t (NBLK == 128 == blockDim).
    {
        bool ok = (t <= qb) && (is_u8 ? (lb[qb * NBLK + t] != 0)
                                      : (lw[qb * NBLK + t] != 0u));
        uint32_t m = __ballot_sync(0xffffffffu, ok);
        if (lane == 0) wmask[warp] = m;

        // Q tile load (coalesced) in the same phase
        #pragma unroll
        for (int it = 0; it < 2; it++) {
            int f = t + it * 128;
            int row = f >> 4, cc = f & 15;
            float4 v = *(const float4*)(base + (size_t)(qb * BLK + row) * INNER3 + h * DH + cc * 4);
            *(float4*)(qs + row * SP + cc * 4) = v;
        }
        __syncthreads();

        // Compact: position = popc of earlier-warp masks + earlier lanes
        int before = 0;
        #pragma unroll
        for (int w2 = 0; w2 < 4; w2++)
            if (w2 < warp) before += __popc(wmask[w2]);
        if (ok) {
            int pos = before + __popc(wmask[warp] & ((1u << lane) - 1u));
            jlist[pos] = t;
        }
    }
    __syncthreads();
    const int count = __popc(wmask[0]) + __popc(wmask[1]) +
                      __popc(wmask[2]) + __popc(wmask[3]);

    // cp.async issue of K/V tiles for list entry i into stage i&1.
    auto issue = [&](int i) {
        const int jb = jlist[i];
        const int st = i & 1;
        #pragma unroll
        for (int it = 0; it < 2; it++) {
            int f = t + it * 128;
            int row = f >> 4, cc = f & 15;
            const float* rowp = base + (size_t)(jb * BLK + row) * INNER3 + h * DH + cc * 4;
            cp_async16(smem_u32(&ks[st][row * SP + cc * 4]), rowp + DIM);
            cp_async16(smem_u32(&vs[st][row * SP + cc * 4]), rowp + 2 * DIM);
        }
        cp_commit();
    };

    float m0 = -1e30f, l0 = 0.f, m1 = -1e30f, l1 = 0.f;
    float4 o0 = make_float4(0.f, 0.f, 0.f, 0.f);
    float4 o1 = make_float4(0.f, 0.f, 0.f, 0.f);
    const float scale = 0.125f;   // 1/sqrt(64)

    if (count > 0) issue(0);

    for (int i = 0; i < count; i++) {
        const int jb = jlist[i];
        const int st = i & 1;
        if (i + 1 < count) { issue(i + 1); cp_wait1(); }
        else               { cp_wait0(); }
        __syncthreads();   // stage st fully landed for all threads

        // Scores: thread computes S[r0][c], S[r1][c]
        float s0 = 0.f, s1 = 0.f;
        {
            const float4* kp = (const float4*)(&ks[st][c * SP]);
            const float4* q0 = (const float4*)(qs + r0 * SP);
            const float4* q1 = (const float4*)(qs + r1 * SP);
            #pragma unroll
            for (int d = 0; d < 16; d++) {
                float4 kk = kp[d];
                float4 a0 = q0[d];
                float4 a1 = q1[d];
                s0 += a0.x * kk.x + a0.y * kk.y + a0.z * kk.z + a0.w * kk.w;
                s1 += a1.x * kk.x + a1.y * kk.y + a1.z * kk.z + a1.w * kk.w;
            }
        }
        s0 *= scale;
        s1 *= scale;
        if (jb == qb) {                     // causal within diagonal block
            if (c > r0) s0 = -1e30f;
            if (c > r1) s1 = -1e30f;
        }

        // Row max over the 16-lane column group
        float mr0 = s0, mr1 = s1;
        #pragma unroll
        for (int k = 1; k < 16; k <<= 1) {
            mr0 = fmaxf(mr0, __shfl_xor_sync(0xffffffffu, mr0, k, 32));
            mr1 = fmaxf(mr1, __shfl_xor_sync(0xffffffffu, mr1, k, 32));
        }
        float mn0 = fmaxf(m0, mr0);
        float mn1 = fmaxf(m1, mr1);
        float p0  = __expf(s0 - mn0);
        float p1  = __expf(s1 - mn1);
        float cr0 = __expf(m0 - mn0);
        float cr1 = __expf(m1 - mn1);

        // Row sum
        float sm0 = p0, sm1 = p1;
        #pragma unroll
        for (int k = 1; k < 16; k <<= 1) {
            sm0 += __shfl_xor_sync(0xffffffffu, sm0, k, 32);
            sm1 += __shfl_xor_sync(0xffffffffu, sm1, k, 32);
        }
        l0 = l0 * cr0 + sm0;  m0 = mn0;
        l1 = l1 * cr1 + sm1;  m1 = mn1;
        o0.x *= cr0; o0.y *= cr0; o0.z *= cr0; o0.w *= cr0;
        o1.x *= cr1; o1.y *= cr1; o1.z *= cr1; o1.w *= cr1;

        // O[r][c0..c0+3] += P[r][:] @ V[:, c0..c0+3]; P broadcast via shuffle.
        #pragma unroll
        for (int j = 0; j < 16; j++) {
            float pj0 = __shfl_sync(0xffffffffu, p0, lanebase | j, 32);
            float pj1 = __shfl_sync(0xffffffffu, p1, lanebase | j, 32);
            float4 vv = *(const float4*)(&vs[st][j * SP + c0]);
            o0.x += pj0 * vv.x; o0.y += pj0 * vv.y; o0.z += pj0 * vv.z; o0.w += pj0 * vv.w;
            o1.x += pj1 * vv.x; o1.y += pj1 * vv.y; o1.z += pj1 * vv.z; o1.w += pj1 * vv.w;
        }
        __syncthreads();   // all reads of stage st done before it is refilled
    }

    // Epilogue: normalize and write bf16 hi/lo split directly (gemm2 input).
    const float inv0 = 1.f / l0;
    const float inv1 = 1.f / l1;
    const size_t ob0 = (size_t)(b * SEQ + qb * BLK + r0) * DIM + h * DH + c0;
    const size_t ob1 = (size_t)(b * SEQ + qb * BLK + r1) * DIM + h * DH + c0;

    float v0[4] = { o0.x * inv0, o0.y * inv0, o0.z * inv0, o0.w * inv0 };
    float v1[4] = { o1.x * inv1, o1.y * inv1, o1.z * inv1, o1.w * inv1 };

    __nv_bfloat162 h0a, h0b, l0a, l0b, h1a, h1b, l1a, l1b;
    h0a.x = __float2bfloat16(v0[0]); h0a.y = __float2bfloat16(v0[1]);
    h0b.x = __float2bfloat16(v0[2]); h0b.y = __float2bfloat16(v0[3]);
    l0a.x = __float2bfloat16(v0[0] - __bfloat162float(h0a.x));
    l0a.y = __float2bfloat16(v0[1] - __bfloat162float(h0a.y));
    l0b.x = __float2bfloat16(v0[2] - __bfloat162float(h0b.x));
    l0b.y = __float2bfloat16(v0[3] - __bfloat162float(h0b.y));
    h1a.x = __float2bfloat16(v1[0]); h1a.y = __float2bfloat16(v1[1]);
    h1b.x = __float2bfloat16(v1[2]); h1b.y = __float2bfloat16(v1[3]);
    l1a.x = __float2bfloat16(v1[0] - __bfloat162float(h1a.x));
    l1a.y = __float2bfloat16(v1[1] - __bfloat162float(h1a.y));
    l1b.x = __float2bfloat16(v1[2] - __bfloat162float(h1b.x));
    l1b.y = __float2bfloat16(v1[3] - __bfloat162float(h1b.y));

    *(__nv_bfloat162*)(g_a_hi + ob0)     = h0a;
    *(__nv_bfloat162*)(g_a_hi + ob0 + 2) = h0b;
    *(__nv_bfloat162*)(g_a_lo + ob0)     = l0a;
    *(__nv_bfloat162*)(g_a_lo + ob0 + 2) = l0b;
    *(__nv_bfloat162*)(g_a_hi + ob1)     = h1a;
    *(__nv_bfloat162*)(g_a_hi + ob1 + 2) = h1b;
    *(__nv_bfloat162*)(g_a_lo + ob1)     = l1a;
    *(__nv_bfloat162*)(g_a_lo + ob1 + 2) = l1b;
}

// ---------------------------------------------------------------------------
// Inputs: 0:x [2,2048,1024] f32  1:w_qkv [1024,3072] f32
//         2:w_out [1024,1024] f32  3:b_out [1024] f32  4:layout [128,128] bool
// Output: [2,2048,1024] f32
// ---------------------------------------------------------------------------
extern "C" void kernel_launch(void* const* d_in, const int* in_sizes, int n_in,
                              void* d_out, int out_size)
{
    const float* x      = (const float*)d_in[0];
    const float* w_qkv  = (const float*)d_in[1];
    const float* w_out  = (const float*)d_in[2];
    const float* b_out  = (const float*)d_in[3];
    const void*  layout = d_in[4];
    float* out = (float*)d_out;

    cudaFuncSetAttribute(tc_gemm1_kernel,
                         cudaFuncAttributeMaxDynamicSharedMemorySize, SM_GEMM);
    cudaFuncSetAttribute(tc_gemm2_kernel,
                         cudaFuncAttributeMaxDynamicSharedMemorySize, SM_GEMM);

    // Prep: weight transposes + splits, x split
    {
        dim3 g1(INNER3 / 32, GK / 32);
        tsp_wq_kernel<<<g1, 256>>>(w_qkv);
        dim3 g2(DIM / 32, GK / 32);
        tsp_wo_kernel<<<g2, 256>>>(w_out);
        split_x_kernel<<<(BATCH * SEQ * DIM) / (256 * 4), 256>>>(x);
    }
    // 1) QKV projection (HMMA bf16-split): [4096,1024] @ [1024,3072] -> g_qkv
    {
        dim3 grid(INNER3 / 128, (BATCH * SEQ) / 128);
        tc_gemm1_kernel<<<grid, 256, SM_GEMM>>>();
    }
    // 2) Block-sparse causal attention -> g_a_hi/g_a_lo (bf16 split, fused)
    {
        dim3 grid(NBLK, HEADS, BATCH);
        sparse_attn_kernel<<<grid, 128>>>(layout);
    }
    // 3) Output projection (HMMA) + bias -> out
    {
        dim3 grid(DIM / 128, (BATCH * SEQ) / 128);
        tc_gemm2_kernel<<<grid, 256, SM_GEMM>>>(b_out, out);
    }
}

// round 12
// speedup vs baseline: 1.0761x; 1.0047x over previous
#include <cuda_runtime.h>
#include <cuda_bf16.h>
#include <cstdint>

// Problem constants
#define BATCH   2
#define SEQ     2048
#define HEADS   16
#define DH      64
#define DIM     1024
#define INNER3  3072
#define NBLK    128
#define BLK     16
#define GK      1024        // K dim of both GEMMs

// Scratch (no allocations allowed -> device globals)
__device__ float g_qkv [(size_t)BATCH * SEQ * INNER3];  // [b*n, 3072]: q|k|v
__device__ __align__(16) __nv_bfloat16 g_a_hi [(size_t)BATCH * SEQ * DIM];   // split A (x, then attn)
__device__ __align__(16) __nv_bfloat16 g_a_lo [(size_t)BATCH * SEQ * DIM];
__device__ __align__(16) __nv_bfloat16 g_wq_hi[(size_t)INNER3 * DIM];        // w_qkv^T split [N,K]
__device__ __align__(16) __nv_bfloat16 g_wq_lo[(size_t)INNER3 * DIM];
__device__ __align__(16) __nv_bfloat16 g_wo_hi[(size_t)DIM * DIM];           // w_out^T split [N,K]
__device__ __align__(16) __nv_bfloat16 g_wo_lo[(size_t)DIM * DIM];

// ---------------------------------------------------------------------------
// Async-copy + packed-f32x2 helpers
// ---------------------------------------------------------------------------
__device__ __forceinline__ uint32_t smem_u32(const void* p) {
    uint32_t a;
    asm("{ .reg .u64 t; cvta.to.shared.u64 t, %1; cvt.u32.u64 %0, t; }"
        : "=r"(a) : "l"(p));
    return a;
}
__device__ __forceinline__ void cp_async16(uint32_t dst, const void* src) {
    asm volatile("cp.async.cg.shared.global [%0], [%1], 16;" :: "r"(dst), "l"(src));
}
__device__ __forceinline__ void cp_commit() {
    asm volatile("cp.async.commit_group;");
}
__device__ __forceinline__ void cp_wait0() {
    asm volatile("cp.async.wait_group 0;" ::: "memory");
}
__device__ __forceinline__ void cp_wait1() {
    asm volatile("cp.async.wait_group 1;" ::: "memory");
}
__device__ __forceinline__ void mma_bf16(float c[4], uint32_t a0, uint32_t a1,
                                         uint32_t a2, uint32_t a3,
                                         uint32_t b0, uint32_t b1) {
    asm volatile(
        "mma.sync.aligned.m16n8k16.row.col.f32.bf16.bf16.f32 "
        "{%0,%1,%2,%3}, {%4,%5,%6,%7}, {%8,%9}, {%0,%1,%2,%3};"
        : "+f"(c[0]), "+f"(c[1]), "+f"(c[2]), "+f"(c[3])
        : "r"(a0), "r"(a1), "r"(a2), "r"(a3), "r"(b0), "r"(b1));
}
// Packed fp32x2 (Blackwell family baseline; SASS FFMA2)
__device__ __forceinline__ void ffma2(unsigned long long& c,
                                      unsigned long long a, unsigned long long b) {
    asm("fma.rn.f32x2 %0, %1, %2, %0;" : "+l"(c) : "l"(a), "l"(b));
}
__device__ __forceinline__ void fmul2(unsigned long long& c, unsigned long long b) {
    asm("mul.rn.f32x2 %0, %0, %1;" : "+l"(c) : "l"(b));
}
__device__ __forceinline__ unsigned long long pack2(float x, float y) {
    unsigned long long r;
    asm("mov.b64 %0, {%1,%2};" : "=l"(r) : "f"(x), "f"(y));
    return r;
}
__device__ __forceinline__ void unpack2(unsigned long long p, float& x, float& y) {
    asm("mov.b64 {%0,%1}, %2;" : "=f"(x), "=f"(y) : "l"(p));
}

// ---------------------------------------------------------------------------
// HMMA bf16-split GEMM (unchanged from the passing round-8 kernel).
// ---------------------------------------------------------------------------
#define BK      32
#define ROWP    40                         // padded row length in bf16
#define ARR_B   (128 * ROWP * 2)           // 10240 bytes per array
#define STG_B   (4 * ARR_B)                // 40960 bytes per stage
#define SM_GEMM (2 * STG_B)                // 81920

template <bool HAS_BIAS>
__device__ __forceinline__ void hmma_gemm_body(
    const __nv_bfloat16* __restrict__ Ahi, const __nv_bfloat16* __restrict__ Alo,
    const __nv_bfloat16* __restrict__ Bhi, const __nv_bfloat16* __restrict__ Blo,
    const float* __restrict__ bias, float* __restrict__ C, int Ntot)
{
    extern __shared__ char dsm[];
    const uint32_t smb = smem_u32(dsm);

    const int t    = threadIdx.x;          // 0..255
    const int lane = t & 31;
    const int wid  = t >> 5;               // 0..7
    const int wm   = wid >> 2;             // 0..1
    const int wn   = wid & 3;              // 0..3
    const int gid  = lane >> 2;            // 0..7
    const int tg   = lane & 3;             // 0..3
    const int bn0  = blockIdx.x * 128;
    const int bm0  = blockIdx.y * 128;

    float acc[4][4][4];
    #pragma unroll
    for (int i = 0; i < 4; i++)
        #pragma unroll
        for (int j = 0; j < 4; j++)
            #pragma unroll
            for (int k = 0; k < 4; k++) acc[i][j][k] = 0.f;

    const __nv_bfloat16* gA[2] = { Ahi + (size_t)bm0 * GK, Alo + (size_t)bm0 * GK };
    const __nv_bfloat16* gB[2] = { Bhi + (size_t)bn0 * GK, Blo + (size_t)bn0 * GK };

    auto load_stage = [&](int stage, int kofs) {
        const uint32_t base = smb + stage * STG_B;
        #pragma unroll
        for (int arr = 0; arr < 4; arr++) {          // 0:Ah 1:Al 2:Bh 3:Bl
            const __nv_bfloat16* src = (arr < 2) ? gA[arr] : gB[arr - 2];
            const uint32_t dst0 = base + arr * ARR_B;
            #pragma unroll
            for (int i = 0; i < 2; i++) {
                int idx = t + i * 256;               // 0..511
                int row = idx >> 2;                  // 0..127
                int c16 = idx & 3;                   // 0..3
                cp_async16(dst0 + row * (ROWP * 2) + c16 * 16,
                           src + (size_t)row * GK + kofs + c16 * 8);
            }
        }
        cp_commit();
    };

    load_stage(0, 0);
    cp_wait0();
    __syncthreads();

    int cur = 0;
    for (int kc = 0; kc < GK / BK; kc++) {
        const int nxt = cur ^ 1;
        if (kc + 1 < GK / BK) load_stage(nxt, (kc + 1) * BK);

        const uint32_t* Ah = (const uint32_t*)(dsm + cur * STG_B + 0 * ARR_B);
        const uint32_t* Al = (const uint32_t*)(dsm + cur * STG_B + 1 * ARR_B);
        const uint32_t* Bh = (const uint32_t*)(dsm + cur * STG_B + 2 * ARR_B);
        const uint32_t* Bl = (const uint32_t*)(dsm + cur * STG_B + 3 * ARR_B);

        #pragma unroll
        for (int ks = 0; ks < 2; ks++) {             // two k16 steps per BK=32
            const int ko = ks * 8 + tg;              // u32 column offset
            uint32_t ah[4][4], al[4][4], bh[4][2], bl[4][2];
            #pragma unroll
            for (int mf = 0; mf < 4; mf++) {
                int rb = (wm * 64 + mf * 16 + gid) * (ROWP / 2) + ko;
                ah[mf][0] = Ah[rb];
                ah[mf][1] = Ah[rb + 8 * (ROWP / 2)];
                ah[mf][2] = Ah[rb + 4];
                ah[mf][3] = Ah[rb + 8 * (ROWP / 2) + 4];
                al[mf][0] = Al[rb];
                al[mf][1] = Al[rb + 8 * (ROWP / 2)];
                al[mf][2] = Al[rb + 4];
                al[mf][3] = Al[rb + 8 * (ROWP / 2) + 4];
            }
            #pragma unroll
            for (int nf = 0; nf < 4; nf++) {
                int nb = (wn * 32 + nf * 8 + gid) * (ROWP / 2) + ko;
                bh[nf][0] = Bh[nb];
                bh[nf][1] = Bh[nb + 4];
                bl[nf][0] = Bl[nb];
                bl[nf][1] = Bl[nb + 4];
            }
            #pragma unroll
            for (int mf = 0; mf < 4; mf++)
                #pragma unroll
                for (int nf = 0; nf < 4; nf++) {
                    mma_bf16(acc[mf][nf], ah[mf][0], ah[mf][1], ah[mf][2], ah[mf][3],
                             bh[nf][0], bh[nf][1]);
                    mma_bf16(acc[mf][nf], ah[mf][0], ah[mf][1], ah[mf][2], ah[mf][3],
                             bl[nf][0], bl[nf][1]);
                    mma_bf16(acc[mf][nf], al[mf][0], al[mf][1], al[mf][2], al[mf][3],
                             bh[nf][0], bh[nf][1]);
                }
        }

        cp_wait0();
        __syncthreads();
        cur = nxt;
    }

    #pragma unroll
    for (int mf = 0; mf < 4; mf++) {
        int row = bm0 + wm * 64 + mf * 16 + gid;
        #pragma unroll
        for (int nf = 0; nf < 4; nf++) {
            int col = bn0 + wn * 32 + nf * 8 + tg * 2;
            float bx = 0.f, by = 0.f;
            if (HAS_BIAS) { bx = bias[col]; by = bias[col + 1]; }
            float2 v0 = make_float2(acc[mf][nf][0] + bx, acc[mf][nf][1] + by);
            float2 v1 = make_float2(acc[mf][nf][2] + bx, acc[mf][nf][3] + by);
            *(float2*)(C + (size_t)row * Ntot + col)       = v0;
            *(float2*)(C + (size_t)(row + 8) * Ntot + col) = v1;
        }
    }
}

__global__ __launch_bounds__(256) void tc_gemm1_kernel()
{
    hmma_gemm_body<false>(g_a_hi, g_a_lo, g_wq_hi, g_wq_lo, nullptr, g_qkv, INNER3);
}

__global__ __launch_bounds__(256) void tc_gemm2_kernel(const float* __restrict__ bias,
                                                       float* __restrict__ out)
{
    hmma_gemm_body<true>(g_a_hi, g_a_lo, g_wo_hi, g_wo_lo, bias, out, DIM);
}

// ---------------------------------------------------------------------------
// fp32 -> (bf16 hi, bf16 lo) elementwise split for x. 4 elems/thread.
// ---------------------------------------------------------------------------
__global__ __launch_bounds__(256) void split_x_kernel(const float* __restrict__ x)
{
    const int i0 = (blockIdx.x * 256 + threadIdx.x) * 4;
    float4 v = *(const float4*)(x + i0);
    __nv_bfloat16 h0 = __float2bfloat16(v.x);
    __nv_bfloat16 h1 = __float2bfloat16(v.y);
    __nv_bfloat16 h2 = __float2bfloat16(v.z);
    __nv_bfloat16 h3 = __float2bfloat16(v.w);
    __nv_bfloat16 l0 = __float2bfloat16(v.x - __bfloat162float(h0));
    __nv_bfloat16 l1 = __float2bfloat16(v.y - __bfloat162float(h1));
    __nv_bfloat16 l2 = __float2bfloat16(v.z - __bfloat162float(h2));
    __nv_bfloat16 l3 = __float2bfloat16(v.w - __bfloat162float(h3));
    __nv_bfloat162 hh0; hh0.x = h0; hh0.y = h1;
    __nv_bfloat162 hh1; hh1.x = h2; hh1.y = h3;
    __nv_bfloat162 ll0; ll0.x = l0; ll0.y = l1;
    __nv_bfloat162 ll1; ll1.x = l2; ll1.y = l3;
    *(__nv_bfloat162*)(g_a_hi + i0)     = hh0;
    *(__nv_bfloat162*)(g_a_hi + i0 + 2) = hh1;
    *(__nv_bfloat162*)(g_a_lo + i0)     = ll0;
    *(__nv_bfloat162*)(g_a_lo + i0 + 2) = ll1;
}

// ---------------------------------------------------------------------------
// Transpose + split: src [GK x N] fp32 -> dst_hi/lo [N x GK] bf16
// ---------------------------------------------------------------------------
__device__ __forceinline__ void tsp_body(const float* __restrict__ src,
                                         __nv_bfloat16* __restrict__ dhi,
                                         __nv_bfloat16* __restrict__ dlo, int N)
{
    __shared__ float tile[32][33];
    const int bx = blockIdx.x * 32;   // N offset
    const int by = blockIdx.y * 32;   // K offset
    const int tx = threadIdx.x & 31;
    const int ty = threadIdx.x >> 5;  // 0..7
    #pragma unroll
    for (int i = 0; i < 4; i++)
        tile[ty + i * 8][tx] = src[(size_t)(by + ty + i * 8) * N + bx + tx];
    __syncthreads();
    #pragma unroll
    for (int i = 0; i < 4; i++) {
        float v = tile[tx][ty + i * 8];
        __nv_bfloat16 h = __float2bfloat16(v);
        __nv_bfloat16 l = __float2bfloat16(v - __bfloat162float(h));
        size_t o = (size_t)(bx + ty + i * 8) * GK + by + tx;
        dhi[o] = h;
        dlo[o] = l;
    }
}

__global__ __launch_bounds__(256) void tsp_wq_kernel(const float* __restrict__ w)
{
    tsp_body(w, g_wq_hi, g_wq_lo, INNER3);
}
__global__ __launch_bounds__(256) void tsp_wo_kernel(const float* __restrict__ w)
{
    tsp_body(w, g_wo_hi, g_wo_lo, DIM);
}

// ---------------------------------------------------------------------------
// Block-sparse causal attention, cp.async double-buffered + packed f32x2 math.
// grid = (NBLK, HEADS, BATCH), 128 threads.
// Score loop: packed (even,odd) dim-pair partial sums -> FFMA2, no packing movs.
// PV loop: packed (o.x,o.y)/(o.z,o.w) accumulators, p_j dup-packed once per j.
// Epilogue writes the bf16 hi/lo split directly (gemm2 input).
// ---------------------------------------------------------------------------
#define SP 68   // smem row stride in floats: 272B, 16B-aligned, 2-way max conflict

__global__ __launch_bounds__(128) void sparse_attn_kernel(const void* __restrict__ layout_raw)
{
    const int qb = blockIdx.x;
    const int h  = blockIdx.y;
    const int b  = blockIdx.z;

    const int t    = threadIdx.x;     // 0..127
    const int c    = t & 15;
    const int rp   = t >> 4;          // 0..7
    const int r0   = rp * 2;
    const int r1   = rp * 2 + 1;
    const int c0   = c * 4;
    const int lanebase = t & 16;
    const int warp = t >> 5;
    const int lane = t & 31;

    __shared__ float    qs[16 * SP];
    __shared__ float    ks[2][16 * SP];
    __shared__ float    vs[2][16 * SP];
    __shared__ int      jlist[NBLK];
    __shared__ uint32_t wmask[4];

    const unsigned char* lb = (const unsigned char*)layout_raw;
    const bool is_u8 = (lb[128] != 0);
    const uint32_t* lw = (const uint32_t*)layout_raw;

    const float* base = g_qkv + (size_t)b * SEQ * INNER3;

    // Ballot pass: thread t checks jb = t (NBLK == 128 == blockDim).
    {
        bool ok = (t <= qb) && (is_u8 ? (lb[qb * NBLK + t] != 0)
                                      : (lw[qb * NBLK + t] != 0u));
        uint32_t m = __ballot_sync(0xffffffffu, ok);
        if (lane == 0) wmask[warp] = m;

        // Q tile load (coalesced) in the same phase
        #pragma unroll
        for (int it = 0; it < 2; it++) {
            int f = t + it * 128;
            int row = f >> 4, cc = f & 15;
            float4 v = *(const float4*)(base + (size_t)(qb * BLK + row) * INNER3 + h * DH + cc * 4);
            *(float4*)(qs + row * SP + cc * 4) = v;
        }
        __syncthreads();

        int before = 0;
        #pragma unroll
        for (int w2 = 0; w2 < 4; w2++)
            if (w2 < warp) before += __popc(wmask[w2]);
        if (ok) {
            int pos = before + __popc(wmask[warp] & ((1u << lane) - 1u));
            jlist[pos] = t;
        }
    }
    __syncthreads();
    const int count = __popc(wmask[0]) + __popc(wmask[1]) +
                      __popc(wmask[2]) + __popc(wmask[3]);

    auto issue = [&](int i) {
        const int jb = jlist[i];
        const int st = i & 1;
        #pragma unroll
        for (int it = 0; it < 2; it++) {
            int f = t + it * 128;
            int row = f >> 4, cc = f & 15;
            const float* rowp = base + (size_t)(jb * BLK + row) * INNER3 + h * DH + cc * 4;
            cp_async16(smem_u32(&ks[st][row * SP + cc * 4]), rowp + DIM);
            cp_async16(smem_u32(&vs[st][row * SP + cc * 4]), rowp + 2 * DIM);
        }
        cp_commit();
    };

    float m0 = -1e30f, l0 = 0.f, m1 = -1e30f, l1 = 0.f;
    unsigned long long o0xy = 0ull, o0zw = 0ull, o1xy = 0ull, o1zw = 0ull;
    const float scale = 0.125f;   // 1/sqrt(64)

    if (count > 0) issue(0);

    for (int i = 0; i < count; i++) {
        const int jb = jlist[i];
        const int st = i & 1;
        if (i + 1 < count) { issue(i + 1); cp_wait1(); }
        else               { cp_wait0(); }
        __syncthreads();   // stage st fully landed for all threads

        // Scores via packed dim-pair FFMA2: s = (even-sum, odd-sum), hadd at end
        unsigned long long s0p = 0ull, s1p = 0ull;
        {
            const ulonglong2* kp = (const ulonglong2*)(&ks[st][c * SP]);
            const ulonglong2* q0 = (const ulonglong2*)(qs + r0 * SP);
            const ulonglong2* q1 = (const ulonglong2*)(qs + r1 * SP);
            #pragma unroll
            for (int d = 0; d < 16; d++) {
                ulonglong2 kk = kp[d];
                ulonglong2 a0 = q0[d];
                ulonglong2 a1 = q1[d];
                ffma2(s0p, a0.x, kk.x);
                ffma2(s0p, a0.y, kk.y);
                ffma2(s1p, a1.x, kk.x);
                ffma2(s1p, a1.y, kk.y);
            }
        }
        float sa, sb, s0, s1;
        unpack2(s0p, sa, sb); s0 = (sa + sb) * scale;
        unpack2(s1p, sa, sb); s1 = (sa + sb) * scale;
        if (jb == qb) {                     // causal within diagonal block
            if (c > r0) s0 = -1e30f;
            if (c > r1) s1 = -1e30f;
        }

        // Row max over the 16-lane column group
        float mr0 = s0, mr1 = s1;
        #pragma unroll
        for (int k = 1; k < 16; k <<= 1) {
            mr0 = fmaxf(mr0, __shfl_xor_sync(0xffffffffu, mr0, k, 32));
            mr1 = fmaxf(mr1, __shfl_xor_sync(0xffffffffu, mr1, k, 32));
        }
        float mn0 = fmaxf(m0, mr0);
        float mn1 = fmaxf(m1, mr1);
        float p0  = __expf(s0 - mn0);
        float p1  = __expf(s1 - mn1);
        float cr0 = __expf(m0 - mn0);
        float cr1 = __expf(m1 - mn1);

        // Row sum
        float sm0 = p0, sm1 = p1;
        #pragma unroll
        for (int k = 1; k < 16; k <<= 1) {
            sm0 += __shfl_xor_sync(0xffffffffu, sm0, k, 32);
            sm1 += __shfl_xor_sync(0xffffffffu, sm1, k, 32);
        }
        l0 = l0 * cr0 + sm0;  m0 = mn0;
        l1 = l1 * cr1 + sm1;  m1 = mn1;
        {
            unsigned long long c0d = pack2(cr0, cr0);
            unsigned long long c1d = pack2(cr1, cr1);
            fmul2(o0xy, c0d); fmul2(o0zw, c0d);
            fmul2(o1xy, c1d); fmul2(o1zw, c1d);
        }

        // O[r][c0..c0+3] += P[r][:] @ V[:, c0..c0+3]; packed over components.
        #pragma unroll
        for (int j = 0; j < 16; j++) {
            float pj0 = __shfl_sync(0xffffffffu, p0, lanebase | j, 32);
            float pj1 = __shfl_sync(0xffffffffu, p1, lanebase | j, 32);
            unsigned long long pj0d = pack2(pj0, pj0);
            unsigned long long pj1d = pack2(pj1, pj1);
            ulonglong2 vv = *(const ulonglong2*)(&vs[st][j * SP + c0]);
            ffma2(o0xy, vv.x, pj0d);
            ffma2(o0zw, vv.y, pj0d);
            ffma2(o1xy, vv.x, pj1d);
            ffma2(o1zw, vv.y, pj1d);
        }
        __syncthreads();   // all reads of stage st done before it is refilled
    }

    // Epilogue: normalize and write bf16 hi/lo split directly (gemm2 input).
    const float inv0 = 1.f / l0;
    const float inv1 = 1.f / l1;
    const size_t ob0 = (size_t)(b * SEQ + qb * BLK + r0) * DIM + h * DH + c0;
    const size_t ob1 = (size_t)(b * SEQ + qb * BLK + r1) * DIM + h * DH + c0;

    float v0[4], v1[4];
    unpack2(o0xy, v0[0], v0[1]);
    unpack2(o0zw, v0[2], v0[3]);
    unpack2(o1xy, v1[0], v1[1]);
    unpack2(o1zw, v1[2], v1[3]);
    #pragma unroll
    for (int k = 0; k < 4; k++) { v0[k] *= inv0; v1[k] *= inv1; }

    __nv_bfloat162 h0a, h0b, l0a, l0b, h1a, h1b, l1a, l1b;
    h0a.x = __float2bfloat16(v0[0]); h0a.y = __float2bfloat16(v0[1]);
    h0b.x = __float2bfloat16(v0[2]); h0b.y = __float2bfloat16(v0[3]);
    l0a.x = __float2bfloat16(v0[0] - __bfloat162float(h0a.x));
    l0a.y = __float2bfloat16(v0[1] - __bfloat162float(h0a.y));
    l0b.x = __float2bfloat16(v0[2] - __bfloat162float(h0b.x));
    l0b.y = __float2bfloat16(v0[3] - __bfloat162float(h0b.y));
    h1a.x = __float2bfloat16(v1[0]); h1a.y = __float2bfloat16(v1[1]);
    h1b.x = __float2bfloat16(v1[2]); h1b.y = __float2bfloat16(v1[3]);
    l1a.x = __float2bfloat16(v1[0] - __bfloat162float(h1a.x));
    l1a.y = __float2bfloat16(v1[1] - __bfloat162float(h1a.y));
    l1b.x = __float2bfloat16(v1[2] - __bfloat162float(h1b.x));
    l1b.y = __float2bfloat16(v1[3] - __bfloat162float(h1b.y));

    *(__nv_bfloat162*)(g_a_hi + ob0)     = h0a;
    *(__nv_bfloat162*)(g_a_hi + ob0 + 2) = h0b;
    *(__nv_bfloat162*)(g_a_lo + ob0)     = l0a;
    *(__nv_bfloat162*)(g_a_lo + ob0 + 2) = l0b;
    *(__nv_bfloat162*)(g_a_hi + ob1)     = h1a;
    *(__nv_bfloat162*)(g_a_hi + ob1 + 2) = h1b;
    *(__nv_bfloat162*)(g_a_lo + ob1)     = l1a;
    *(__nv_bfloat162*)(g_a_lo + ob1 + 2) = l1b;
}

// ---------------------------------------------------------------------------
// Inputs: 0:x [2,2048,1024] f32  1:w_qkv [1024,3072] f32
//         2:w_out [1024,1024] f32  3:b_out [1024] f32  4:layout [128,128] bool
// Output: [2,2048,1024] f32
// ---------------------------------------------------------------------------
extern "C" void kernel_launch(void* const* d_in, const int* in_sizes, int n_in,
                              void* d_out, int out_size)
{
    const float* x      = (const float*)d_in[0];
    const float* w_qkv  = (const float*)d_in[1];
    const float* w_out  = (const float*)d_in[2];
    const float* b_out  = (const float*)d_in[3];
    const void*  layout = d_in[4];
    float* out = (float*)d_out;

    cudaFuncSetAttribute(tc_gemm1_kernel,
                         cudaFuncAttributeMaxDynamicSharedMemorySize, SM_GEMM);
    cudaFuncSetAttribute(tc_gemm2_kernel,
                         cudaFuncAttributeMaxDynamicSharedMemorySize, SM_GEMM);

    // Prep: weight transposes + splits, x split
    {
        dim3 g1(INNER3 / 32, GK / 32);
        tsp_wq_kernel<<<g1, 256>>>(w_qkv);
        dim3 g2(DIM / 32, GK / 32);
        tsp_wo_kernel<<<g2, 256>>>(w_out);
        split_x_kernel<<<(BATCH * SEQ * DIM) / (256 * 4), 256>>>(x);
    }
    // 1) QKV projection (HMMA bf16-split): [4096,1024] @ [1024,3072] -> g_qkv
    {
        dim3 grid(INNER3 / 128, (BATCH * SEQ) / 128);
        tc_gemm1_kernel<<<grid, 256, SM_GEMM>>>();
    }
    // 2) Block-sparse causal attention -> g_a_hi/g_a_lo (bf16 split, fused)
    {
        dim3 grid(NBLK, HEADS, BATCH);
        sparse_attn_kernel<<<grid, 128>>>(layout);
    }
    // 3) Output projection (HMMA) + bias -> out
    {
        dim3 grid(DIM / 128, (BATCH * SEQ) / 128);
        tc_gemm2_kernel<<<grid, 256, SM_GEMM>>>(b_out, out);
    }
}

// round 15
// speedup vs baseline: 1.4370x; 1.3353x over previous
#include <cuda_runtime.h>
#include <cuda_bf16.h>
#include <cstdint>

// Problem constants
#define BATCH   2
#define SEQ     2048
#define HEADS   16
#define DH      64
#define DIM     1024
#define INNER3  3072
#define NBLK    128
#define BLK     16
#define GK      1024        // K dim of both GEMMs

// Scratch (no allocations allowed -> device globals)
__device__ float g_qkv [(size_t)BATCH * SEQ * INNER3];  // [b*n, 3072]: q|k|v
__device__ __align__(16) __nv_bfloat16 g_a_hi [(size_t)BATCH * SEQ * DIM];   // split A (x, then attn)
__device__ __align__(16) __nv_bfloat16 g_a_lo [(size_t)BATCH * SEQ * DIM];
__device__ __align__(16) __nv_bfloat16 g_wq_hi[(size_t)INNER3 * DIM];        // w_qkv^T split [N,K]
__device__ __align__(16) __nv_bfloat16 g_wq_lo[(size_t)INNER3 * DIM];
__device__ __align__(16) __nv_bfloat16 g_wo_hi[(size_t)DIM * DIM];           // w_out^T split [N,K]
__device__ __align__(16) __nv_bfloat16 g_wo_lo[(size_t)DIM * DIM];
// Attention operands (precomputed bf16 splits)
__device__ __align__(16) __nv_bfloat16 g_k_hi [(size_t)BATCH * SEQ * DIM];   // K  [b*n, h*64+d]
__device__ __align__(16) __nv_bfloat16 g_k_lo [(size_t)BATCH * SEQ * DIM];
__device__ __align__(16) __nv_bfloat16 g_vt_hi[(size_t)BATCH * HEADS * DH * SEQ]; // V^T [b,h,d,n]
__device__ __align__(16) __nv_bfloat16 g_vt_lo[(size_t)BATCH * HEADS * DH * SEQ];

// ---------------------------------------------------------------------------
// Helpers
// ---------------------------------------------------------------------------
__device__ __forceinline__ uint32_t smem_u32(const void* p) {
    uint32_t a;
    asm("{ .reg .u64 t; cvta.to.shared.u64 t, %1; cvt.u32.u64 %0, t; }"
        : "=r"(a) : "l"(p));
    return a;
}
__device__ __forceinline__ void cp_async16(uint32_t dst, const void* src) {
    asm volatile("cp.async.cg.shared.global [%0], [%1], 16;" :: "r"(dst), "l"(src));
}
__device__ __forceinline__ void cp_commit() {
    asm volatile("cp.async.commit_group;");
}
__device__ __forceinline__ void cp_wait0() {
    asm volatile("cp.async.wait_group 0;" ::: "memory");
}
__device__ __forceinline__ void cp_wait1() {
    asm volatile("cp.async.wait_group 1;" ::: "memory");
}
__device__ __forceinline__ void cp_wait2() {
    asm volatile("cp.async.wait_group 2;" ::: "memory");
}
__device__ __forceinline__ void mma_bf16(float c[4], uint32_t a0, uint32_t a1,
                                         uint32_t a2, uint32_t a3,
                                         uint32_t b0, uint32_t b1) {
    asm volatile(
        "mma.sync.aligned.m16n8k16.row.col.f32.bf16.bf16.f32 "
        "{%0,%1,%2,%3}, {%4,%5,%6,%7}, {%8,%9}, {%0,%1,%2,%3};"
        : "+f"(c[0]), "+f"(c[1]), "+f"(c[2]), "+f"(c[3])
        : "r"(a0), "r"(a1), "r"(a2), "r"(a3), "r"(b0), "r"(b1));
}
// pack (lo, hi) floats -> bf16x2 (lo in low half)
__device__ __forceinline__ uint32_t cvt2(float lo, float hi) {
    uint32_t r;
    asm("cvt.rn.bf16x2.f32 %0, %1, %2;" : "=r"(r) : "f"(hi), "f"(lo));
    return r;
}
__device__ __forceinline__ float bl_lo(uint32_t p) { return __uint_as_float(p << 16); }
__device__ __forceinline__ float bl_hi(uint32_t p) { return __uint_as_float(p & 0xffff0000u); }

// ---------------------------------------------------------------------------
// HMMA bf16-split GEMM (unchanged from the passing round-8 kernel).
// ---------------------------------------------------------------------------
#define BK      32
#define ROWP    40
#define ARR_B   (128 * ROWP * 2)
#define STG_B   (4 * ARR_B)
#define SM_GEMM (2 * STG_B)

template <bool HAS_BIAS>
__device__ __forceinline__ void hmma_gemm_body(
    const __nv_bfloat16* __restrict__ Ahi, const __nv_bfloat16* __restrict__ Alo,
    const __nv_bfloat16* __restrict__ Bhi, const __nv_bfloat16* __restrict__ Blo,
    const float* __restrict__ bias, float* __restrict__ C, int Ntot)
{
    extern __shared__ char dsm[];
    const uint32_t smb = smem_u32(dsm);

    const int t    = threadIdx.x;
    const int lane = t & 31;
    const int wid  = t >> 5;
    const int wm   = wid >> 2;
    const int wn   = wid & 3;
    const int gid  = lane >> 2;
    const int tg   = lane & 3;
    const int bn0  = blockIdx.x * 128;
    const int bm0  = blockIdx.y * 128;

    float acc[4][4][4];
    #pragma unroll
    for (int i = 0; i < 4; i++)
        #pragma unroll
        for (int j = 0; j < 4; j++)
            #pragma unroll
            for (int k = 0; k < 4; k++) acc[i][j][k] = 0.f;

    const __nv_bfloat16* gA[2] = { Ahi + (size_t)bm0 * GK, Alo + (size_t)bm0 * GK };
    const __nv_bfloat16* gB[2] = { Bhi + (size_t)bn0 * GK, Blo + (size_t)bn0 * GK };

    auto load_stage = [&](int stage, int kofs) {
        const uint32_t base = smb + stage * STG_B;
        #pragma unroll
        for (int arr = 0; arr < 4; arr++) {
            const __nv_bfloat16* src = (arr < 2) ? gA[arr] : gB[arr - 2];
            const uint32_t dst0 = base + arr * ARR_B;
            #pragma unroll
            for (int i = 0; i < 2; i++) {
                int idx = t + i * 256;
                int row = idx >> 2;
                int c16 = idx & 3;
                cp_async16(dst0 + row * (ROWP * 2) + c16 * 16,
                           src + (size_t)row * GK + kofs + c16 * 8);
            }
        }
        cp_commit();
    };

    load_stage(0, 0);
    cp_wait0();
    __syncthreads();

    int cur = 0;
    for (int kc = 0; kc < GK / BK; kc++) {
        const int nxt = cur ^ 1;
        if (kc + 1 < GK / BK) load_stage(nxt, (kc + 1) * BK);

        const uint32_t* Ah = (const uint32_t*)(dsm + cur * STG_B + 0 * ARR_B);
        const uint32_t* Al = (const uint32_t*)(dsm + cur * STG_B + 1 * ARR_B);
        const uint32_t* Bh = (const uint32_t*)(dsm + cur * STG_B + 2 * ARR_B);
        const uint32_t* Bl = (const uint32_t*)(dsm + cur * STG_B + 3 * ARR_B);

        #pragma unroll
        for (int ks = 0; ks < 2; ks++) {
            const int ko = ks * 8 + tg;
            uint32_t ah[4][4], al[4][4], bh[4][2], bl[4][2];
            #pragma unroll
            for (int mf = 0; mf < 4; mf++) {
                int rb = (wm * 64 + mf * 16 + gid) * (ROWP / 2) + ko;
                ah[mf][0] = Ah[rb];
                ah[mf][1] = Ah[rb + 8 * (ROWP / 2)];
                ah[mf][2] = Ah[rb + 4];
                ah[mf][3] = Ah[rb + 8 * (ROWP / 2) + 4];
                al[mf][0] = Al[rb];
                al[mf][1] = Al[rb + 8 * (ROWP / 2)];
                al[mf][2] = Al[rb + 4];
                al[mf][3] = Al[rb + 8 * (ROWP / 2) + 4];
            }
            #pragma unroll
            for (int nf = 0; nf < 4; nf++) {
                int nb = (wn * 32 + nf * 8 + gid) * (ROWP / 2) + ko;
                bh[nf][0] = Bh[nb];
                bh[nf][1] = Bh[nb + 4];
                bl[nf][0] = Bl[nb];
                bl[nf][1] = Bl[nb + 4];
            }
            #pragma unroll
            for (int mf = 0; mf < 4; mf++)
                #pragma unroll
                for (int nf = 0; nf < 4; nf++) {
                    mma_bf16(acc[mf][nf], ah[mf][0], ah[mf][1], ah[mf][2], ah[mf][3],
                             bh[nf][0], bh[nf][1]);
                    mma_bf16(acc[mf][nf], ah[mf][0], ah[mf][1], ah[mf][2], ah[mf][3],
                             bl[nf][0], bl[nf][1]);
                    mma_bf16(acc[mf][nf], al[mf][0], al[mf][1], al[mf][2], al[mf][3],
                             bh[nf][0], bh[nf][1]);
                }
        }

        cp_wait0();
        __syncthreads();
        cur = nxt;
    }

    #pragma unroll
    for (int mf = 0; mf < 4; mf++) {
        int row = bm0 + wm * 64 + mf * 16 + gid;
        #pragma unroll
        for (int nf = 0; nf < 4; nf++) {
            int col = bn0 + wn * 32 + nf * 8 + tg * 2;
            float bx = 0.f, by = 0.f;
            if (HAS_BIAS) { bx = bias[col]; by = bias[col + 1]; }
            float2 v0 = make_float2(acc[mf][nf][0] + bx, acc[mf][nf][1] + by);
            float2 v1 = make_float2(acc[mf][nf][2] + bx, acc[mf][nf][3] + by);
            *(float2*)(C + (size_t)row * Ntot + col)       = v0;
            *(float2*)(C + (size_t)(row + 8) * Ntot + col) = v1;
        }
    }
}

__global__ __launch_bounds__(256) void tc_gemm1_kernel()
{
    hmma_gemm_body<false>(g_a_hi, g_a_lo, g_wq_hi, g_wq_lo, nullptr, g_qkv, INNER3);
}

__global__ __launch_bounds__(256) void tc_gemm2_kernel(const float* __restrict__ bias,
                                                       float* __restrict__ out)
{
    hmma_gemm_body<true>(g_a_hi, g_a_lo, g_wo_hi, g_wo_lo, bias, out, DIM);
}

// ---------------------------------------------------------------------------
// fp32 -> (bf16 hi, bf16 lo) elementwise split for x. 4 elems/thread.
// ---------------------------------------------------------------------------
__global__ __launch_bounds__(256) void split_x_kernel(const float* __restrict__ x)
{
    const int i0 = (blockIdx.x * 256 + threadIdx.x) * 4;
    float4 v = *(const float4*)(x + i0);
    uint32_t h0 = cvt2(v.x, v.y);
    uint32_t h1 = cvt2(v.z, v.w);
    uint32_t l0 = cvt2(v.x - bl_lo(h0), v.y - bl_hi(h0));
    uint32_t l1 = cvt2(v.z - bl_lo(h1), v.w - bl_hi(h1));
    *(uint32_t*)(g_a_hi + i0)     = h0;
    *(uint32_t*)(g_a_hi + i0 + 2) = h1;
    *(uint32_t*)(g_a_lo + i0)     = l0;
    *(uint32_t*)(g_a_lo + i0 + 2) = l1;
}

// K section of g_qkv -> bf16 hi/lo (same layout)
__global__ __launch_bounds__(256) void k_split_kernel()
{
    const int i0 = (blockIdx.x * 256 + threadIdx.x) * 4;
    const int row = i0 >> 10, col = i0 & 1023;
    float4 v = *(const float4*)(g_qkv + (size_t)row * INNER3 + DIM + col);
    uint32_t h0 = cvt2(v.x, v.y);
    uint32_t h1 = cvt2(v.z, v.w);
    uint32_t l0 = cvt2(v.x - bl_lo(h0), v.y - bl_hi(h0));
    uint32_t l1 = cvt2(v.z - bl_lo(h1), v.w - bl_hi(h1));
    *(uint32_t*)(g_k_hi + i0)     = h0;
    *(uint32_t*)(g_k_hi + i0 + 2) = h1;
    *(uint32_t*)(g_k_lo + i0)     = l0;
    *(uint32_t*)(g_k_lo + i0 + 2) = l1;
}

// V section of g_qkv -> transposed bf16 hi/lo: g_vt[(b,h,d), n]
__global__ __launch_bounds__(256) void vt_split_kernel()
{
    __shared__ float tile[32][33];
    const int bx = blockIdx.x * 32;           // n offset
    const int by = blockIdx.y * 32;           // d offset
    const int bh = blockIdx.z;                // b*16 + h
    const int b  = bh >> 4, h = bh & 15;
    const int tx = threadIdx.x & 31;
    const int ty = threadIdx.x >> 5;          // 0..7
    #pragma unroll
    for (int i = 0; i < 4; i++) {
        int n = bx + ty + i * 8;
        tile[ty + i * 8][tx] = g_qkv[(size_t)(b * SEQ + n) * INNER3 + 2 * DIM + h * DH + by + tx];
    }
    __syncthreads();
    #pragma unroll
    for (int i = 0; i < 4; i++) {
        int d = by + ty + i * 8;
        int n = bx + tx;
        float v = tile[tx][ty + i * 8];
        __nv_bfloat16 hv = __float2bfloat16(v);
        __nv_bfloat16 lv = __float2bfloat16(v - __bfloat162float(hv));
        size_t o = (size_t)(bh * DH + d) * SEQ + n;
        g_vt_hi[o] = hv;
        g_vt_lo[o] = lv;
    }
}

// ---------------------------------------------------------------------------
// Transpose + split: src [GK x N] fp32 -> dst_hi/lo [N x GK] bf16
// ---------------------------------------------------------------------------
__device__ __forceinline__ void tsp_body(const float* __restrict__ src,
                                         __nv_bfloat16* __restrict__ dhi,
                                         __nv_bfloat16* __restrict__ dlo, int N)
{
    __shared__ float tile[32][33];
    const int bx = blockIdx.x * 32;
    const int by = blockIdx.y * 32;
    const int tx = threadIdx.x & 31;
    const int ty = threadIdx.x >> 5;
    #pragma unroll
    for (int i = 0; i < 4; i++)
        tile[ty + i * 8][tx] = src[(size_t)(by + ty + i * 8) * N + bx + tx];
    __syncthreads();
    #pragma unroll
    for (int i = 0; i < 4; i++) {
        float v = tile[tx][ty + i * 8];
        __nv_bfloat16 h = __float2bfloat16(v);
        __nv_bfloat16 l = __float2bfloat16(v - __bfloat162float(h));
        size_t o = (size_t)(bx + ty + i * 8) * GK + by + tx;
        dhi[o] = h;
        dlo[o] = l;
    }
}

__global__ __launch_bounds__(256) void tsp_wq_kernel(const float* __restrict__ w)
{
    tsp_body(w, g_wq_hi, g_wq_lo, INNER3);
}
__global__ __launch_bounds__(256) void tsp_wo_kernel(const float* __restrict__ w)
{
    tsp_body(w, g_wo_hi, g_wo_lo, DIM);
}

// ---------------------------------------------------------------------------
// Block-sparse causal attention on HMMA (FA2 fragment style).
// grid = (NBLK, HEADS, BATCH), 128 threads = 4 warps.
// Warp w independently processes allowed blocks w, w+4, ... (split softmax);
// partials merged at the end via smem. Per block: S = Q@K^T (24 mma, bf16
// split), fragment-layout softmax, P@V (24 mma). K tiles double-buffered via
// per-warp cp.async groups; no __syncthreads in the main loop.
// Per-warp smem region (15360B): khi[2]@0/2304, klo[2]@4608/6912,
// vthi@9216, vtlo@12288. Merge staging reuses own region.
// ---------------------------------------------------------------------------
#define AT_REGION 15360
#define AT_KHI    0
#define AT_KLO    4608
#define AT_VTHI   9216
#define AT_VTLO   12288
#define AT_JLIST  61440
#define AT_WMASK  61952
#define SM_ATT    62208

__global__ __launch_bounds__(128) void sparse_attn_kernel(const void* __restrict__ layout_raw)
{
    extern __shared__ char asmem[];
    const int qb = blockIdx.x, h = blockIdx.y, b = blockIdx.z;
    const int t = threadIdx.x, lane = t & 31, w = t >> 5;
    const int gid = lane >> 2, tg = lane & 3;
    char* wb = asmem + w * AT_REGION;
    int* jlist = (int*)(asmem + AT_JLIST);
    uint32_t* wmask = (uint32_t*)(asmem + AT_WMASK);

    // Layout dtype auto-detect (layout[1][0] deterministically true).
    const unsigned char* lb = (const unsigned char*)layout_raw;
    const bool is_u8 = (lb[128] != 0);
    const uint32_t* lwp = (const uint32_t*)layout_raw;

    // Ballot + compaction: thread t checks jb = t.
    {
        bool ok = (t <= qb) && (is_u8 ? (lb[qb * NBLK + t] != 0)
                                      : (lwp[qb * NBLK + t] != 0u));
        uint32_t m = __ballot_sync(0xffffffffu, ok);
        if (lane == 0) wmask[w] = m;
        __syncthreads();
        int before = 0;
        #pragma unroll
        for (int w2 = 0; w2 < 4; w2++)
            if (w2 < w) before += __popc(wmask[w2]);
        if (ok) jlist[before + __popc(wmask[w] & ((1u << lane) - 1u))] = t;
    }
    __syncthreads();
    const int count = __popc(wmask[0]) + __popc(wmask[1]) +
                      __popc(wmask[2]) + __popc(wmask[3]);
    const int myn = (count > w) ? ((count - w + 3) >> 2) : 0;

    // Q a-fragments (hi/lo), straight from g_qkv fp32.
    uint32_t qh[4][4], ql[4][4];
    {
        const float* qp = g_qkv + (size_t)(b * SEQ + qb * BLK) * INNER3 + h * DH;
        #pragma unroll
        for (int kc = 0; kc < 4; kc++) {
            float2 v0 = *(const float2*)(qp + (size_t)gid * INNER3       + kc * 16 + tg * 2);
            float2 v1 = *(const float2*)(qp + (size_t)(gid + 8) * INNER3 + kc * 16 + tg * 2);
            float2 v2 = *(const float2*)(qp + (size_t)gid * INNER3       + kc * 16 + 8 + tg * 2);
            float2 v3 = *(const float2*)(qp + (size_t)(gid + 8) * INNER3 + kc * 16 + 8 + tg * 2);
            float2 vv[4] = { v0, v1, v2, v3 };
            #pragma unroll
            for (int r = 0; r < 4; r++) {
                uint32_t hp = cvt2(vv[r].x, vv[r].y);
                qh[kc][r] = hp;
                ql[kc][r] = cvt2(vv[r].x - bl_lo(hp), vv[r].y - bl_hi(hp));
            }
        }
    }

    float m0 = -1e30f, m1 = -1e30f, l0 = 0.f, l1 = 0.f;
    float o[8][4];
    #pragma unroll
    for (int i = 0; i < 8; i++) { o[i][0] = o[i][1] = o[i][2] = o[i][3] = 0.f; }

    auto issueK = [&](int jb, int st) {
        #pragma unroll
        for (int q = 0; q < 4; q++) {
            int c = lane + q * 32;
            int row = c >> 3, part = c & 7;
            size_t src = (size_t)(b * SEQ + jb * BLK + row) * DIM + h * DH + part * 8;
            cp_async16(smem_u32(wb + AT_KHI + st * 2304 + row * 144 + part * 16), g_k_hi + src);
            cp_async16(smem_u32(wb + AT_KLO + st * 2304 + row * 144 + part * 16), g_k_lo + src);
        }
        cp_commit();
    };
    auto issueV = [&](int jb) {
        #pragma unroll
        for (int q = 0; q < 4; q++) {
            int c = lane + q * 32;
            int d = c >> 1, half = c & 1;
            size_t src = (size_t)((b * HEADS + h) * DH + d) * SEQ + jb * BLK + half * 8;
            cp_async16(smem_u32(wb + AT_VTHI + d * 48 + half * 16), g_vt_hi + src);
            cp_async16(smem_u32(wb + AT_VTLO + d * 48 + half * 16), g_vt_lo + src);
        }
        cp_commit();
    };

    if (myn > 0) issueK(jlist[w], 0);

    for (int idx = 0; idx < myn; idx++) {
        const int i  = w + idx * 4;
        const int jb = jlist[i];
        const int st = idx & 1;
        const bool hn = (idx + 1 < myn);
        issueV(jb);
        if (hn) issueK(jlist[i + 4], st ^ 1);
        // groups outstanding: K_i, V_i (, K_next). Need K_i:
        if (hn) cp_wait2(); else cp_wait1();

        // ---- S = Q @ K^T ----
        float sc0[4] = {0.f, 0.f, 0.f, 0.f};
        float sc1[4] = {0.f, 0.f, 0.f, 0.f};
        {
            const char* kh = wb + AT_KHI + st * 2304;
            const char* kl = wb + AT_KLO + st * 2304;
            #pragma unroll
            for (int kc = 0; kc < 4; kc++) {
                int of0 = gid * 144 + kc * 32 + tg * 4;
                int of1 = (gid + 8) * 144 + kc * 32 + tg * 4;
                uint32_t b0h = *(const uint32_t*)(kh + of0);
                uint32_t b1h = *(const uint32_t*)(kh + of0 + 16);
                uint32_t b0l = *(const uint32_t*)(kl + of0);
                uint32_t b1l = *(const uint32_t*)(kl + of0 + 16);
                mma_bf16(sc0, qh[kc][0], qh[kc][1], qh[kc][2], qh[kc][3], b0h, b1h);
                mma_bf16(sc0, qh[kc][0], qh[kc][1], qh[kc][2], qh[kc][3], b0l, b1l);
                mma_bf16(sc0, ql[kc][0], ql[kc][1], ql[kc][2], ql[kc][3], b0h, b1h);
                uint32_t c0h = *(const uint32_t*)(kh + of1);
                uint32_t c1h = *(const uint32_t*)(kh + of1 + 16);
                uint32_t c0l = *(const uint32_t*)(kl + of1);
                uint32_t c1l = *(const uint32_t*)(kl + of1 + 16);
                mma_bf16(sc1, qh[kc][0], qh[kc][1], qh[kc][2], qh[kc][3], c0h, c1h);
                mma_bf16(sc1, qh[kc][0], qh[kc][1], qh[kc][2], qh[kc][3], c0l, c1l);
                mma_bf16(sc1, ql[kc][0], ql[kc][1], ql[kc][2], ql[kc][3], c0h, c1h);
            }
        }

        // ---- fragment-layout online softmax ----
        float p00 = sc0[0] * 0.125f, p01 = sc0[1] * 0.125f;   // row gid,  keys tg*2,+1
        float p02 = sc0[2] * 0.125f, p03 = sc0[3] * 0.125f;   // row gid+8
        float p10 = sc1[0] * 0.125f, p11 = sc1[1] * 0.125f;   // row gid,  keys 8+tg*2,+1
        float p12 = sc1[2] * 0.125f, p13 = sc1[3] * 0.125f;   // row gid+8
        if (jb == qb) {                                       // causal in diag block
            int ca = tg * 2, cb = ca + 1, cc2 = ca + 8, cd = ca + 9;
            if (ca  > gid) p00 = -1e30f;
            if (cb  > gid) p01 = -1e30f;
            if (cc2 > gid) p10 = -1e30f;
            if (cd  > gid) p11 = -1e30f;
            if (cc2 > gid + 8) p12 = -1e30f;
            if (cd  > gid + 8) p13 = -1e30f;
        }
        float rm0 = fmaxf(fmaxf(p00, p01), fmaxf(p10, p11));
        float rm1 = fmaxf(fmaxf(p02, p03), fmaxf(p12, p13));
        rm0 = fmaxf(rm0, __shfl_xor_sync(0xffffffffu, rm0, 1, 32));
        rm0 = fmaxf(rm0, __shfl_xor_sync(0xffffffffu, rm0, 2, 32));
        rm1 = fmaxf(rm1, __shfl_xor_sync(0xffffffffu, rm1, 1, 32));
        rm1 = fmaxf(rm1, __shfl_xor_sync(0xffffffffu, rm1, 2, 32));
        float mn0 = fmaxf(m0, rm0), mn1 = fmaxf(m1, rm1);
        float cr0 = __expf(m0 - mn0), cr1 = __expf(m1 - mn1);
        p00 = __expf(p00 - mn0); p01 = __expf(p01 - mn0);
        p10 = __expf(p10 - mn0); p11 = __expf(p11 - mn0);
        p02 = __expf(p02 - mn1); p03 = __expf(p03 - mn1);
        p12 = __expf(p12 - mn1); p13 = __expf(p13 - mn1);
        float sum0 = p00 + p01 + p10 + p11;
        float sum1 = p02 + p03 + p12 + p13;
        sum0 += __shfl_xor_sync(0xffffffffu, sum0, 1, 32);
        sum0 += __shfl_xor_sync(0xffffffffu, sum0, 2, 32);
        sum1 += __shfl_xor_sync(0xffffffffu, sum1, 1, 32);
        sum1 += __shfl_xor_sync(0xffffffffu, sum1, 2, 32);
        l0 = l0 * cr0 + sum0; m0 = mn0;
        l1 = l1 * cr1 + sum1; m1 = mn1;
        #pragma unroll
        for (int nt = 0; nt < 8; nt++) {
            o[nt][0] *= cr0; o[nt][1] *= cr0;
            o[nt][2] *= cr1; o[nt][3] *= cr1;
        }

        // P a-fragments (C-layout reuse): a0=(gid,k=tg*2) a1=(gid+8) a2/a3 k+8
        uint32_t pa0h = cvt2(p00, p01), pa1h = cvt2(p02, p03);
        uint32_t pa2h = cvt2(p10, p11), pa3h = cvt2(p12, p13);
        uint32_t pa0l = cvt2(p00 - bl_lo(pa0h), p01 - bl_hi(pa0h));
        uint32_t pa1l = cvt2(p02 - bl_lo(pa1h), p03 - bl_hi(pa1h));
        uint32_t pa2l = cvt2(p10 - bl_lo(pa2h), p11 - bl_hi(pa2h));
        uint32_t pa3l = cvt2(p12 - bl_lo(pa3h), p13 - bl_hi(pa3h));

        // Need V_i:
        if (hn) cp_wait1(); else cp_wait0();

        // ---- O += P @ V  (B = V^T tile [dh][key]) ----
        {
            const char* vh = wb + AT_VTHI;
            const char* vl = wb + AT_VTLO;
            #pragma unroll
            for (int nt = 0; nt < 8; nt++) {
                int off = (nt * 8 + gid) * 48 + tg * 4;
                uint32_t b0h = *(const uint32_t*)(vh + off);
                uint32_t b1h = *(const uint32_t*)(vh + off + 16);
                uint32_t b0l = *(const uint32_t*)(vl + off);
                uint32_t b1l = *(const uint32_t*)(vl + off + 16);
                mma_bf16(o[nt], pa0h, pa1h, pa2h, pa3h, b0h, b1h);
                mma_bf16(o[nt], pa0h, pa1h, pa2h, pa3h, b0l, b1l);
                mma_bf16(o[nt], pa0l, pa1l, pa2l, pa3l, b0h, b1h);
            }
        }
    }

    // ---- merge 4 warp partials ----
    {
        float* ost = (float*)wb;              // 16x64 fp32 (reuses own K region)
        float* mst = (float*)(wb + 4096);     // 16 floats
        float* lst = (float*)(wb + 4160);     // 16 floats
        #pragma unroll
        for (int nt = 0; nt < 8; nt++) {
            int col = nt * 8 + tg * 2;
            ost[gid * 64 + col]           = o[nt][0];
            ost[gid * 64 + col + 1]       = o[nt][1];
            ost[(gid + 8) * 64 + col]     = o[nt][2];
            ost[(gid + 8) * 64 + col + 1] = o[nt][3];
        }
        if (tg == 0) {
            mst[gid] = m0; mst[gid + 8] = m1;
            lst[gid] = l0; lst[gid + 8] = l1;
        }
    }
    __syncthreads();
    {
        const int r  = t >> 3;
        const int d0 = (t & 7) * 8;
        float mw[4], lw2[4];
        #pragma unroll
        for (int w2 = 0; w2 < 4; w2++) {
            mw[w2]  = *(const float*)(asmem + w2 * AT_REGION + 4096 + r * 4);
            lw2[w2] = *(const float*)(asmem + w2 * AT_REGION + 4160 + r * 4);
        }
        float ms = fmaxf(fmaxf(mw[0], mw[1]), fmaxf(mw[2], mw[3]));
        float e[4], lt = 0.f;
        #pragma unroll
        for (int w2 = 0; w2 < 4; w2++) { e[w2] = __expf(mw[w2] - ms); lt += e[w2] * lw2[w2]; }
        float acc[8];
        #pragma unroll
        for (int dd = 0; dd < 8; dd++) acc[dd] = 0.f;
        #pragma unroll
        for (int w2 = 0; w2 < 4; w2++) {
            const float* op = (const float*)(asmem + w2 * AT_REGION) + r * 64 + d0;
            float ew = e[w2];
            #pragma unroll
            for (int dd = 0; dd < 8; dd++) acc[dd] += ew * op[dd];
        }
        float inv = 1.f / lt;
        size_t ob = (size_t)(b * SEQ + qb * BLK + r) * DIM + h * DH + d0;
        #pragma unroll
        for (int dd = 0; dd < 8; dd += 2) {
            float x = acc[dd] * inv, y = acc[dd + 1] * inv;
            uint32_t hp = cvt2(x, y);
            uint32_t lp = cvt2(x - bl_lo(hp), y - bl_hi(hp));
            *(uint32_t*)(g_a_hi + ob + dd) = hp;
            *(uint32_t*)(g_a_lo + ob + dd) = lp;
        }
    }
}

// ---------------------------------------------------------------------------
// Inputs: 0:x [2,2048,1024] f32  1:w_qkv [1024,3072] f32
//         2:w_out [1024,1024] f32  3:b_out [1024] f32  4:layout [128,128] bool
// Output: [2,2048,1024] f32
// ---------------------------------------------------------------------------
extern "C" void kernel_launch(void* const* d_in, const int* in_sizes, int n_in,
                              void* d_out, int out_size)
{
    const float* x      = (const float*)d_in[0];
    const float* w_qkv  = (const float*)d_in[1];
    const float* w_out  = (const float*)d_in[2];
    const float* b_out  = (const float*)d_in[3];
    const void*  layout = d_in[4];
    float* out = (float*)d_out;

    cudaFuncSetAttribute(tc_gemm1_kernel,
                         cudaFuncAttributeMaxDynamicSharedMemorySize, SM_GEMM);
    cudaFuncSetAttribute(tc_gemm2_kernel,
                         cudaFuncAttributeMaxDynamicSharedMemorySize, SM_GEMM);
    cudaFuncSetAttribute(sparse_attn_kernel,
                         cudaFuncAttributeMaxDynamicSharedMemorySize, SM_ATT);

    // Prep: weight transposes + splits, x split
    {
        dim3 g1(INNER3 / 32, GK / 32);
        tsp_wq_kernel<<<g1, 256>>>(w_qkv);
        dim3 g2(DIM / 32, GK / 32);
        tsp_wo_kernel<<<g2, 256>>>(w_out);
        split_x_kernel<<<(BATCH * SEQ * DIM) / (256 * 4), 256>>>(x);
    }
    // 1) QKV projection (HMMA): [4096,1024] @ [1024,3072] -> g_qkv
    {
        dim3 grid(INNER3 / 128, (BATCH * SEQ) / 128);
        tc_gemm1_kernel<<<grid, 256, SM_GEMM>>>();
    }
    // 1b) K/V bf16 precompute (K split + V transpose-split)
    {
        k_split_kernel<<<(BATCH * SEQ * DIM) / (256 * 4), 256>>>();
        dim3 gv(SEQ / 32, DH / 32, BATCH * HEADS);
        vt_split_kernel<<<gv, 256>>>();
    }
    // 2) Block-sparse causal attention (HMMA) -> g_a_hi/g_a_lo
    {
        dim3 grid(NBLK, HEADS, BATCH);
        sparse_attn_kernel<<<grid, 128, SM_ATT>>>(layout);
    }
    // 3) Output projection (HMMA) + bias -> out
    {
        dim3 grid(DIM / 128, (BATCH * SEQ) / 128);
        tc_gemm2_kernel<<<grid, 256, SM_GEMM>>>(b_out, out);
    }
}

// round 16
// speedup vs baseline: 1.4535x; 1.0115x over previous
#include <cuda_runtime.h>
#include <cuda_bf16.h>
#include <cstdint>

// Problem constants
#define BATCH   2
#define SEQ     2048
#define HEADS   16
#define DH      64
#define DIM     1024
#define INNER3  3072
#define NBLK    128
#define BLK     16
#define GK      1024        // K dim of both GEMMs

// Scratch (no allocations allowed -> device globals)
__device__ float g_qkv [(size_t)BATCH * SEQ * INNER3];  // [b*n, 3072]: q|k|v
__device__ __align__(16) __nv_bfloat16 g_a_hi [(size_t)BATCH * SEQ * DIM];   // split A (x, then attn)
__device__ __align__(16) __nv_bfloat16 g_a_lo [(size_t)BATCH * SEQ * DIM];
__device__ __align__(16) __nv_bfloat16 g_wq_hi[(size_t)INNER3 * DIM];        // w_qkv^T split [N,K]
__device__ __align__(16) __nv_bfloat16 g_wq_lo[(size_t)INNER3 * DIM];
__device__ __align__(16) __nv_bfloat16 g_wo_hi[(size_t)DIM * DIM];           // w_out^T split [N,K]
__device__ __align__(16) __nv_bfloat16 g_wo_lo[(size_t)DIM * DIM];
// Attention operands (precomputed bf16 splits)
__device__ __align__(16) __nv_bfloat16 g_k_hi [(size_t)BATCH * SEQ * DIM];   // K  [b*n, h*64+d]
__device__ __align__(16) __nv_bfloat16 g_k_lo [(size_t)BATCH * SEQ * DIM];
__device__ __align__(16) __nv_bfloat16 g_vt_hi[(size_t)BATCH * HEADS * DH * SEQ]; // V^T [b,h,d,n]
__device__ __align__(16) __nv_bfloat16 g_vt_lo[(size_t)BATCH * HEADS * DH * SEQ];

// ---------------------------------------------------------------------------
// Helpers
// ---------------------------------------------------------------------------
__device__ __forceinline__ uint32_t smem_u32(const void* p) {
    uint32_t a;
    asm("{ .reg .u64 t; cvta.to.shared.u64 t, %1; cvt.u32.u64 %0, t; }"
        : "=r"(a) : "l"(p));
    return a;
}
__device__ __forceinline__ void cp_async16(uint32_t dst, const void* src) {
    asm volatile("cp.async.cg.shared.global [%0], [%1], 16;" :: "r"(dst), "l"(src));
}
__device__ __forceinline__ void cp_commit() {
    asm volatile("cp.async.commit_group;");
}
__device__ __forceinline__ void cp_wait0() {
    asm volatile("cp.async.wait_group 0;" ::: "memory");
}
__device__ __forceinline__ void cp_wait1() {
    asm volatile("cp.async.wait_group 1;" ::: "memory");
}
__device__ __forceinline__ void cp_wait2() {
    asm volatile("cp.async.wait_group 2;" ::: "memory");
}
__device__ __forceinline__ void mma_bf16(float c[4], uint32_t a0, uint32_t a1,
                                         uint32_t a2, uint32_t a3,
                                         uint32_t b0, uint32_t b1) {
    asm volatile(
        "mma.sync.aligned.m16n8k16.row.col.f32.bf16.bf16.f32 "
        "{%0,%1,%2,%3}, {%4,%5,%6,%7}, {%8,%9}, {%0,%1,%2,%3};"
        : "+f"(c[0]), "+f"(c[1]), "+f"(c[2]), "+f"(c[3])
        : "r"(a0), "r"(a1), "r"(a2), "r"(a3), "r"(b0), "r"(b1));
}
// pack (lo, hi) floats -> bf16x2 (lo in low half)
__device__ __forceinline__ uint32_t cvt2(float lo, float hi) {
    uint32_t r;
    asm("cvt.rn.bf16x2.f32 %0, %1, %2;" : "=r"(r) : "f"(hi), "f"(lo));
    return r;
}
__device__ __forceinline__ float bl_lo(uint32_t p) { return __uint_as_float(p << 16); }
__device__ __forceinline__ float bl_hi(uint32_t p) { return __uint_as_float(p & 0xffff0000u); }

// ---------------------------------------------------------------------------
// HMMA bf16-split GEMM. Round-16: combo-major MMA issue (3 passes of 16
// independent MMAs) so dependent accumulations are 16 issues apart.
// ---------------------------------------------------------------------------
#define BK      32
#define ROWP    40
#define ARR_B   (128 * ROWP * 2)
#define STG_B   (4 * ARR_B)
#define SM_GEMM (2 * STG_B)

template <bool HAS_BIAS>
__device__ __forceinline__ void hmma_gemm_body(
    const __nv_bfloat16* __restrict__ Ahi, const __nv_bfloat16* __restrict__ Alo,
    const __nv_bfloat16* __restrict__ Bhi, const __nv_bfloat16* __restrict__ Blo,
    const float* __restrict__ bias, float* __restrict__ C, int Ntot)
{
    extern __shared__ char dsm[];
    const uint32_t smb = smem_u32(dsm);

    const int t    = threadIdx.x;
    const int lane = t & 31;
    const int wid  = t >> 5;
    const int wm   = wid >> 2;
    const int wn   = wid & 3;
    const int gid  = lane >> 2;
    const int tg   = lane & 3;
    const int bn0  = blockIdx.x * 128;
    const int bm0  = blockIdx.y * 128;

    float acc[4][4][4];
    #pragma unroll
    for (int i = 0; i < 4; i++)
        #pragma unroll
        for (int j = 0; j < 4; j++)
            #pragma unroll
            for (int k = 0; k < 4; k++) acc[i][j][k] = 0.f;

    const __nv_bfloat16* gA[2] = { Ahi + (size_t)bm0 * GK, Alo + (size_t)bm0 * GK };
    const __nv_bfloat16* gB[2] = { Bhi + (size_t)bn0 * GK, Blo + (size_t)bn0 * GK };

    auto load_stage = [&](int stage, int kofs) {
        const uint32_t base = smb + stage * STG_B;
        #pragma unroll
        for (int arr = 0; arr < 4; arr++) {
            const __nv_bfloat16* src = (arr < 2) ? gA[arr] : gB[arr - 2];
            const uint32_t dst0 = base + arr * ARR_B;
            #pragma unroll
            for (int i = 0; i < 2; i++) {
                int idx = t + i * 256;
                int row = idx >> 2;
                int c16 = idx & 3;
                cp_async16(dst0 + row * (ROWP * 2) + c16 * 16,
                           src + (size_t)row * GK + kofs + c16 * 8);
            }
        }
        cp_commit();
    };

    load_stage(0, 0);
    cp_wait0();
    __syncthreads();

    int cur = 0;
    for (int kc = 0; kc < GK / BK; kc++) {
        const int nxt = cur ^ 1;
        if (kc + 1 < GK / BK) load_stage(nxt, (kc + 1) * BK);

        const uint32_t* Ah = (const uint32_t*)(dsm + cur * STG_B + 0 * ARR_B);
        const uint32_t* Al = (const uint32_t*)(dsm + cur * STG_B + 1 * ARR_B);
        const uint32_t* Bh = (const uint32_t*)(dsm + cur * STG_B + 2 * ARR_B);
        const uint32_t* Bl = (const uint32_t*)(dsm + cur * STG_B + 3 * ARR_B);

        #pragma unroll
        for (int ks = 0; ks < 2; ks++) {
            const int ko = ks * 8 + tg;
            uint32_t ah[4][4], al[4][4], bh[4][2], bl[4][2];
            #pragma unroll
            for (int mf = 0; mf < 4; mf++) {
                int rb = (wm * 64 + mf * 16 + gid) * (ROWP / 2) + ko;
                ah[mf][0] = Ah[rb];
                ah[mf][1] = Ah[rb + 8 * (ROWP / 2)];
                ah[mf][2] = Ah[rb + 4];
                ah[mf][3] = Ah[rb + 8 * (ROWP / 2) + 4];
                al[mf][0] = Al[rb];
                al[mf][1] = Al[rb + 8 * (ROWP / 2)];
                al[mf][2] = Al[rb + 4];
                al[mf][3] = Al[rb + 8 * (ROWP / 2) + 4];
            }
            #pragma unroll
            for (int nf = 0; nf < 4; nf++) {
                int nb = (wn * 32 + nf * 8 + gid) * (ROWP / 2) + ko;
                bh[nf][0] = Bh[nb];
                bh[nf][1] = Bh[nb + 4];
                bl[nf][0] = Bl[nb];
                bl[nf][1] = Bl[nb + 4];
            }
            // Combo-major: 3 passes of 16 independent MMAs (dep distance 16)
            #pragma unroll
            for (int mf = 0; mf < 4; mf++)
                #pragma unroll
                for (int nf = 0; nf < 4; nf++)
                    mma_bf16(acc[mf][nf], ah[mf][0], ah[mf][1], ah[mf][2], ah[mf][3],
                             bh[nf][0], bh[nf][1]);
            #pragma unroll
            for (int mf = 0; mf < 4; mf++)
                #pragma unroll
                for (int nf = 0; nf < 4; nf++)
                    mma_bf16(acc[mf][nf], ah[mf][0], ah[mf][1], ah[mf][2], ah[mf][3],
                             bl[nf][0], bl[nf][1]);
            #pragma unroll
            for (int mf = 0; mf < 4; mf++)
                #pragma unroll
                for (int nf = 0; nf < 4; nf++)
                    mma_bf16(acc[mf][nf], al[mf][0], al[mf][1], al[mf][2], al[mf][3],
                             bh[nf][0], bh[nf][1]);
        }

        cp_wait0();
        __syncthreads();
        cur = nxt;
    }

    #pragma unroll
    for (int mf = 0; mf < 4; mf++) {
        int row = bm0 + wm * 64 + mf * 16 + gid;
        #pragma unroll
        for (int nf = 0; nf < 4; nf++) {
            int col = bn0 + wn * 32 + nf * 8 + tg * 2;
            float bx = 0.f, by = 0.f;
            if (HAS_BIAS) { bx = bias[col]; by = bias[col + 1]; }
            float2 v0 = make_float2(acc[mf][nf][0] + bx, acc[mf][nf][1] + by);
            float2 v1 = make_float2(acc[mf][nf][2] + bx, acc[mf][nf][3] + by);
            *(float2*)(C + (size_t)row * Ntot + col)       = v0;
            *(float2*)(C + (size_t)(row + 8) * Ntot + col) = v1;
        }
    }
}

__global__ __launch_bounds__(256) void tc_gemm1_kernel()
{
    hmma_gemm_body<false>(g_a_hi, g_a_lo, g_wq_hi, g_wq_lo, nullptr, g_qkv, INNER3);
}

__global__ __launch_bounds__(256) void tc_gemm2_kernel(const float* __restrict__ bias,
                                                       float* __restrict__ out)
{
    hmma_gemm_body<true>(g_a_hi, g_a_lo, g_wo_hi, g_wo_lo, bias, out, DIM);
}

// ---------------------------------------------------------------------------
// fp32 -> (bf16 hi, bf16 lo) elementwise split for x. 4 elems/thread.
// ---------------------------------------------------------------------------
__global__ __launch_bounds__(256) void split_x_kernel(const float* __restrict__ x)
{
    const int i0 = (blockIdx.x * 256 + threadIdx.x) * 4;
    float4 v = *(const float4*)(x + i0);
    uint32_t h0 = cvt2(v.x, v.y);
    uint32_t h1 = cvt2(v.z, v.w);
    uint32_t l0 = cvt2(v.x - bl_lo(h0), v.y - bl_hi(h0));
    uint32_t l1 = cvt2(v.z - bl_lo(h1), v.w - bl_hi(h1));
    *(uint32_t*)(g_a_hi + i0)     = h0;
    *(uint32_t*)(g_a_hi + i0 + 2) = h1;
    *(uint32_t*)(g_a_lo + i0)     = l0;
    *(uint32_t*)(g_a_lo + i0 + 2) = l1;
}

// K section of g_qkv -> bf16 hi/lo (same layout)
__global__ __launch_bounds__(256) void k_split_kernel()
{
    const int i0 = (blockIdx.x * 256 + threadIdx.x) * 4;
    const int row = i0 >> 10, col = i0 & 1023;
    float4 v = *(const float4*)(g_qkv + (size_t)row * INNER3 + DIM + col);
    uint32_t h0 = cvt2(v.x, v.y);
    uint32_t h1 = cvt2(v.z, v.w);
    uint32_t l0 = cvt2(v.x - bl_lo(h0), v.y - bl_hi(h0));
    uint32_t l1 = cvt2(v.z - bl_lo(h1), v.w - bl_hi(h1));
    *(uint32_t*)(g_k_hi + i0)     = h0;
    *(uint32_t*)(g_k_hi + i0 + 2) = h1;
    *(uint32_t*)(g_k_lo + i0)     = l0;
    *(uint32_t*)(g_k_lo + i0 + 2) = l1;
}

// V section of g_qkv -> transposed bf16 hi/lo: g_vt[(b,h,d), n]
__global__ __launch_bounds__(256) void vt_split_kernel()
{
    __shared__ float tile[32][33];
    const int bx = blockIdx.x * 32;           // n offset
    const int by = blockIdx.y * 32;           // d offset
    const int bh = blockIdx.z;                // b*16 + h
    const int b  = bh >> 4, h = bh & 15;
    const int tx = threadIdx.x & 31;
    const int ty = threadIdx.x >> 5;          // 0..7
    #pragma unroll
    for (int i = 0; i < 4; i++) {
        int n = bx + ty + i * 8;
        tile[ty + i * 8][tx] = g_qkv[(size_t)(b * SEQ + n) * INNER3 + 2 * DIM + h * DH + by + tx];
    }
    __syncthreads();
    #pragma unroll
    for (int i = 0; i < 4; i++) {
        int d = by + ty + i * 8;
        int n = bx + tx;
        float v = tile[tx][ty + i * 8];
        __nv_bfloat16 hv = __float2bfloat16(v);
        __nv_bfloat16 lv = __float2bfloat16(v - __bfloat162float(hv));
        size_t o = (size_t)(bh * DH + d) * SEQ + n;
        g_vt_hi[o] = hv;
        g_vt_lo[o] = lv;
    }
}

// ---------------------------------------------------------------------------
// Transpose + split: src [GK x N] fp32 -> dst_hi/lo [N x GK] bf16
// ---------------------------------------------------------------------------
__device__ __forceinline__ void tsp_body(const float* __restrict__ src,
                                         __nv_bfloat16* __restrict__ dhi,
                                         __nv_bfloat16* __restrict__ dlo, int N)
{
    __shared__ float tile[32][33];
    const int bx = blockIdx.x * 32;
    const int by = blockIdx.y * 32;
    const int tx = threadIdx.x & 31;
    const int ty = threadIdx.x >> 5;
    #pragma unroll
    for (int i = 0; i < 4; i++)
        tile[ty + i * 8][tx] = src[(size_t)(by + ty + i * 8) * N + bx + tx];
    __syncthreads();
    #pragma unroll
    for (int i = 0; i < 4; i++) {
        float v = tile[tx][ty + i * 8];
        __nv_bfloat16 h = __float2bfloat16(v);
        __nv_bfloat16 l = __float2bfloat16(v - __bfloat162float(h));
        size_t o = (size_t)(bx + ty + i * 8) * GK + by + tx;
        dhi[o] = h;
        dlo[o] = l;
    }
}

__global__ __launch_bounds__(256) void tsp_wq_kernel(const float* __restrict__ w)
{
    tsp_body(w, g_wq_hi, g_wq_lo, INNER3);
}
__global__ __launch_bounds__(256) void tsp_wo_kernel(const float* __restrict__ w)
{
    tsp_body(w, g_wo_hi, g_wo_lo, DIM);
}

// ---------------------------------------------------------------------------
// Block-sparse causal attention on HMMA (FA2 fragment style).
// Round-16: S uses 6 independent accumulator chains; PV preloads V fragments
// and issues combo-major (8 independent MMAs per pass).
// ---------------------------------------------------------------------------
#define AT_REGION 15360
#define AT_KHI    0
#define AT_KLO    4608
#define AT_VTHI   9216
#define AT_VTLO   12288
#define AT_JLIST  61440
#define AT_WMASK  61952
#define SM_ATT    62208

__global__ __launch_bounds__(128) void sparse_attn_kernel(const void* __restrict__ layout_raw)
{
    extern __shared__ char asmem[];
    const int qb = blockIdx.x, h = blockIdx.y, b = blockIdx.z;
    const int t = threadIdx.x, lane = t & 31, w = t >> 5;
    const int gid = lane >> 2, tg = lane & 3;
    char* wb = asmem + w * AT_REGION;
    int* jlist = (int*)(asmem + AT_JLIST);
    uint32_t* wmask = (uint32_t*)(asmem + AT_WMASK);

    // Layout dtype auto-detect (layout[1][0] deterministically true).
    const unsigned char* lb = (const unsigned char*)layout_raw;
    const bool is_u8 = (lb[128] != 0);
    const uint32_t* lwp = (const uint32_t*)layout_raw;

    // Ballot + compaction: thread t checks jb = t.
    {
        bool ok = (t <= qb) && (is_u8 ? (lb[qb * NBLK + t] != 0)
                                      : (lwp[qb * NBLK + t] != 0u));
        uint32_t m = __ballot_sync(0xffffffffu, ok);
        if (lane == 0) wmask[w] = m;
        __syncthreads();
        int before = 0;
        #pragma unroll
        for (int w2 = 0; w2 < 4; w2++)
            if (w2 < w) before += __popc(wmask[w2]);
        if (ok) jlist[before + __popc(wmask[w] & ((1u << lane) - 1u))] = t;
    }
    __syncthreads();
    const int count = __popc(wmask[0]) + __popc(wmask[1]) +
                      __popc(wmask[2]) + __popc(wmask[3]);
    const int myn = (count > w) ? ((count - w + 3) >> 2) : 0;

    // Q a-fragments (hi/lo), straight from g_qkv fp32.
    uint32_t qh[4][4], ql[4][4];
    {
        const float* qp = g_qkv + (size_t)(b * SEQ + qb * BLK) * INNER3 + h * DH;
        #pragma unroll
        for (int kc = 0; kc < 4; kc++) {
            float2 v0 = *(const float2*)(qp + (size_t)gid * INNER3       + kc * 16 + tg * 2);
            float2 v1 = *(const float2*)(qp + (size_t)(gid + 8) * INNER3 + kc * 16 + tg * 2);
            float2 v2 = *(const float2*)(qp + (size_t)gid * INNER3       + kc * 16 + 8 + tg * 2);
            float2 v3 = *(const float2*)(qp + (size_t)(gid + 8) * INNER3 + kc * 16 + 8 + tg * 2);
            float2 vv[4] = { v0, v1, v2, v3 };
            #pragma unroll
            for (int r = 0; r < 4; r++) {
                uint32_t hp = cvt2(vv[r].x, vv[r].y);
                qh[kc][r] = hp;
                ql[kc][r] = cvt2(vv[r].x - bl_lo(hp), vv[r].y - bl_hi(hp));
            }
        }
    }

    float m0 = -1e30f, m1 = -1e30f, l0 = 0.f, l1 = 0.f;
    float o[8][4];
    #pragma unroll
    for (int i = 0; i < 8; i++) { o[i][0] = o[i][1] = o[i][2] = o[i][3] = 0.f; }

    auto issueK = [&](int jb, int st) {
        #pragma unroll
        for (int q = 0; q < 4; q++) {
            int c = lane + q * 32;
            int row = c >> 3, part = c & 7;
            size_t src = (size_t)(b * SEQ + jb * BLK + row) * DIM + h * DH + part * 8;
            cp_async16(smem_u32(wb + AT_KHI + st * 2304 + row * 144 + part * 16), g_k_hi + src);
            cp_async16(smem_u32(wb + AT_KLO + st * 2304 + row * 144 + part * 16), g_k_lo + src);
        }
        cp_commit();
    };
    auto issueV = [&](int jb) {
        #pragma unroll
        for (int q = 0; q < 4; q++) {
            int c = lane + q * 32;
            int d = c >> 1, half = c & 1;
            size_t src = (size_t)((b * HEADS + h) * DH + d) * SEQ + jb * BLK + half * 8;
            cp_async16(smem_u32(wb + AT_VTHI + d * 48 + half * 16), g_vt_hi + src);
            cp_async16(smem_u32(wb + AT_VTLO + d * 48 + half * 16), g_vt_lo + src);
        }
        cp_commit();
    };

    if (myn > 0) issueK(jlist[w], 0);

    for (int idx = 0; idx < myn; idx++) {
        const int i  = w + idx * 4;
        const int jb = jlist[i];
        const int st = idx & 1;
        const bool hn = (idx + 1 < myn);
        issueV(jb);
        if (hn) issueK(jlist[i + 4], st ^ 1);
        // groups outstanding: K_i, V_i (, K_next). Need K_i:
        if (hn) cp_wait2(); else cp_wait1();

        // ---- S = Q @ K^T : 6 independent accumulator chains ----
        float s0a[4] = {0.f, 0.f, 0.f, 0.f}, s0b[4] = {0.f, 0.f, 0.f, 0.f},
              s0c[4] = {0.f, 0.f, 0.f, 0.f};
        float s1a[4] = {0.f, 0.f, 0.f, 0.f}, s1b[4] = {0.f, 0.f, 0.f, 0.f},
              s1c[4] = {0.f, 0.f, 0.f, 0.f};
        {
            const char* kh = wb + AT_KHI + st * 2304;
            const char* kl = wb + AT_KLO + st * 2304;
            #pragma unroll
            for (int kc = 0; kc < 4; kc++) {
                int of0 = gid * 144 + kc * 32 + tg * 4;
                int of1 = (gid + 8) * 144 + kc * 32 + tg * 4;
                uint32_t b0h = *(const uint32_t*)(kh + of0);
                uint32_t b1h = *(const uint32_t*)(kh + of0 + 16);
                uint32_t b0l = *(const uint32_t*)(kl + of0);
                uint32_t b1l = *(const uint32_t*)(kl + of0 + 16);
                uint32_t c0h = *(const uint32_t*)(kh + of1);
                uint32_t c1h = *(const uint32_t*)(kh + of1 + 16);
                uint32_t c0l = *(const uint32_t*)(kl + of1);
                uint32_t c1l = *(const uint32_t*)(kl + of1 + 16);
                mma_bf16(s0a, qh[kc][0], qh[kc][1], qh[kc][2], qh[kc][3], b0h, b1h);
                mma_bf16(s1a, qh[kc][0], qh[kc][1], qh[kc][2], qh[kc][3], c0h, c1h);
                mma_bf16(s0b, qh[kc][0], qh[kc][1], qh[kc][2], qh[kc][3], b0l, b1l);
                mma_bf16(s1b, qh[kc][0], qh[kc][1], qh[kc][2], qh[kc][3], c0l, c1l);
                mma_bf16(s0c, ql[kc][0], ql[kc][1], ql[kc][2], ql[kc][3], b0h, b1h);
                mma_bf16(s1c, ql[kc][0], ql[kc][1], ql[kc][2], ql[kc][3], c0h, c1h);
            }
        }
        float sc0[4], sc1[4];
        #pragma unroll
        for (int r = 0; r < 4; r++) {
            sc0[r] = s0a[r] + s0b[r] + s0c[r];
            sc1[r] = s1a[r] + s1b[r] + s1c[r];
        }

        // ---- fragment-layout online softmax ----
        float p00 = sc0[0] * 0.125f, p01 = sc0[1] * 0.125f;   // row gid,  keys tg*2,+1
        float p02 = sc0[2] * 0.125f, p03 = sc0[3] * 0.125f;   // row gid+8
        float p10 = sc1[0] * 0.125f, p11 = sc1[1] * 0.125f;   // row gid,  keys 8+tg*2,+1
        float p12 = sc1[2] * 0.125f, p13 = sc1[3] * 0.125f;   // row gid+8
        if (jb == qb) {                                       // causal in diag block
            int ca = tg * 2, cb = ca + 1, cc2 = ca + 8, cd = ca + 9;
            if (ca  > gid) p00 = -1e30f;
            if (cb  > gid) p01 = -1e30f;
            if (cc2 > gid) p10 = -1e30f;
            if (cd  > gid) p11 = -1e30f;
            if (cc2 > gid + 8) p12 = -1e30f;
            if (cd  > gid + 8) p13 = -1e30f;
        }
        float rm0 = fmaxf(fmaxf(p00, p01), fmaxf(p10, p11));
        float rm1 = fmaxf(fmaxf(p02, p03), fmaxf(p12, p13));
        rm0 = fmaxf(rm0, __shfl_xor_sync(0xffffffffu, rm0, 1, 32));
        rm0 = fmaxf(rm0, __shfl_xor_sync(0xffffffffu, rm0, 2, 32));
        rm1 = fmaxf(rm1, __shfl_xor_sync(0xffffffffu, rm1, 1, 32));
        rm1 = fmaxf(rm1, __shfl_xor_sync(0xffffffffu, rm1, 2, 32));
        float mn0 = fmaxf(m0, rm0), mn1 = fmaxf(m1, rm1);
        float cr0 = __expf(m0 - mn0), cr1 = __expf(m1 - mn1);
        p00 = __expf(p00 - mn0); p01 = __expf(p01 - mn0);
        p10 = __expf(p10 - mn0); p11 = __expf(p11 - mn0);
        p02 = __expf(p02 - mn1); p03 = __expf(p03 - mn1);
        p12 = __expf(p12 - mn1); p13 = __expf(p13 - mn1);
        float sum0 = p00 + p01 + p10 + p11;
        float sum1 = p02 + p03 + p12 + p13;
        sum0 += __shfl_xor_sync(0xffffffffu, sum0, 1, 32);
        sum0 += __shfl_xor_sync(0xffffffffu, sum0, 2, 32);
        sum1 += __shfl_xor_sync(0xffffffffu, sum1, 1, 32);
        sum1 += __shfl_xor_sync(0xffffffffu, sum1, 2, 32);
        l0 = l0 * cr0 + sum0; m0 = mn0;
        l1 = l1 * cr1 + sum1; m1 = mn1;
        #pragma unroll
        for (int nt = 0; nt < 8; nt++) {
            o[nt][0] *= cr0; o[nt][1] *= cr0;
            o[nt][2] *= cr1; o[nt][3] *= cr1;
        }

        // P a-fragments (C-layout reuse)
        uint32_t pa0h = cvt2(p00, p01), pa1h = cvt2(p02, p03);
        uint32_t pa2h = cvt2(p10, p11), pa3h = cvt2(p12, p13);
        uint32_t pa0l = cvt2(p00 - bl_lo(pa0h), p01 - bl_hi(pa0h));
        uint32_t pa1l = cvt2(p02 - bl_lo(pa1h), p03 - bl_hi(pa1h));
        uint32_t pa2l = cvt2(p10 - bl_lo(pa2h), p11 - bl_hi(pa2h));
        uint32_t pa3l = cvt2(p12 - bl_lo(pa3h), p13 - bl_hi(pa3h));

        // Need V_i:
        if (hn) cp_wait1(); else cp_wait0();

        // ---- O += P @ V : preload V fragments, combo-major issue ----
        {
            const char* vh = wb + AT_VTHI;
            const char* vl = wb + AT_VTLO;
            uint32_t vbh[8][2], vbl[8][2];
            #pragma unroll
            for (int nt = 0; nt < 8; nt++) {
                int off = (nt * 8 + gid) * 48 + tg * 4;
                vbh[nt][0] = *(const uint32_t*)(vh + off);
                vbh[nt][1] = *(const uint32_t*)(vh + off + 16);
                vbl[nt][0] = *(const uint32_t*)(vl + off);
                vbl[nt][1] = *(const uint32_t*)(vl + off + 16);
            }
            #pragma unroll
            for (int nt = 0; nt < 8; nt++)
                mma_bf16(o[nt], pa0h, pa1h, pa2h, pa3h, vbh[nt][0], vbh[nt][1]);
            #pragma unroll
            for (int nt = 0; nt < 8; nt++)
                mma_bf16(o[nt], pa0h, pa1h, pa2h, pa3h, vbl[nt][0], vbl[nt][1]);
            #pragma unroll
            for (int nt = 0; nt < 8; nt++)
                mma_bf16(o[nt], pa0l, pa1l, pa2l, pa3l, vbh[nt][0], vbh[nt][1]);
        }
    }

    // ---- merge 4 warp partials ----
    {
        float* ost = (float*)wb;              // 16x64 fp32 (reuses own K region)
        float* mst = (float*)(wb + 4096);     // 16 floats
        float* lst = (float*)(wb + 4160);     // 16 floats
        #pragma unroll
        for (int nt = 0; nt < 8; nt++) {
            int col = nt * 8 + tg * 2;
            ost[gid * 64 + col]           = o[nt][0];
            ost[gid * 64 + col + 1]       = o[nt][1];
            ost[(gid + 8) * 64 + col]     = o[nt][2];
            ost[(gid + 8) * 64 + col + 1] = o[nt][3];
        }
        if (tg == 0) {
            mst[gid] = m0; mst[gid + 8] = m1;
            lst[gid] = l0; lst[gid + 8] = l1;
        }
    }
    __syncthreads();
    {
        const int r  = t >> 3;
        const int d0 = (t & 7) * 8;
        float mw[4], lw2[4];
        #pragma unroll
        for (int w2 = 0; w2 < 4; w2++) {
            mw[w2]  = *(const float*)(asmem + w2 * AT_REGION + 4096 + r * 4);
            lw2[w2] = *(const float*)(asmem + w2 * AT_REGION + 4160 + r * 4);
        }
        float ms = fmaxf(fmaxf(mw[0], mw[1]), fmaxf(mw[2], mw[3]));
        float e[4], lt = 0.f;
        #pragma unroll
        for (int w2 = 0; w2 < 4; w2++) { e[w2] = __expf(mw[w2] - ms); lt += e[w2] * lw2[w2]; }
        float acc[8];
        #pragma unroll
        for (int dd = 0; dd < 8; dd++) acc[dd] = 0.f;
        #pragma unroll
        for (int w2 = 0; w2 < 4; w2++) {
            const float* op = (const float*)(asmem + w2 * AT_REGION) + r * 64 + d0;
            float ew = e[w2];
            #pragma unroll
            for (int dd = 0; dd < 8; dd++) acc[dd] += ew * op[dd];
        }
        float inv = 1.f / lt;
        size_t ob = (size_t)(b * SEQ + qb * BLK + r) * DIM + h * DH + d0;
        #pragma unroll
        for (int dd = 0; dd < 8; dd += 2) {
            float x = acc[dd] * inv, y = acc[dd + 1] * inv;
            uint32_t hp = cvt2(x, y);
            uint32_t lp = cvt2(x - bl_lo(hp), y - bl_hi(hp));
            *(uint32_t*)(g_a_hi + ob + dd) = hp;
            *(uint32_t*)(g_a_lo + ob + dd) = lp;
        }
    }
}

// ---------------------------------------------------------------------------
// Inputs: 0:x [2,2048,1024] f32  1:w_qkv [1024,3072] f32
//         2:w_out [1024,1024] f32  3:b_out [1024] f32  4:layout [128,128] bool
// Output: [2,2048,1024] f32
// ---------------------------------------------------------------------------
extern "C" void kernel_launch(void* const* d_in, const int* in_sizes, int n_in,
                              void* d_out, int out_size)
{
    const float* x      = (const float*)d_in[0];
    const float* w_qkv  = (const float*)d_in[1];
    const float* w_out  = (const float*)d_in[2];
    const float* b_out  = (const float*)d_in[3];
    const void*  layout = d_in[4];
    float* out = (float*)d_out;

    cudaFuncSetAttribute(tc_gemm1_kernel,
                         cudaFuncAttributeMaxDynamicSharedMemorySize, SM_GEMM);
    cudaFuncSetAttribute(tc_gemm2_kernel,
                         cudaFuncAttributeMaxDynamicSharedMemorySize, SM_GEMM);
    cudaFuncSetAttribute(sparse_attn_kernel,
                         cudaFuncAttributeMaxDynamicSharedMemorySize, SM_ATT);

    // Prep: weight transposes + splits, x split
    {
        dim3 g1(INNER3 / 32, GK / 32);
        tsp_wq_kernel<<<g1, 256>>>(w_qkv);
        dim3 g2(DIM / 32, GK / 32);
        tsp_wo_kernel<<<g2, 256>>>(w_out);
        split_x_kernel<<<(BATCH * SEQ * DIM) / (256 * 4), 256>>>(x);
    }
    // 1) QKV projection (HMMA): [4096,1024] @ [1024,3072] -> g_qkv
    {
        dim3 grid(INNER3 / 128, (BATCH * SEQ) / 128);
        tc_gemm1_kernel<<<grid, 256, SM_GEMM>>>();
    }
    // 1b) K/V bf16 precompute (K split + V transpose-split)
    {
        k_split_kernel<<<(BATCH * SEQ * DIM) / (256 * 4), 256>>>();
        dim3 gv(SEQ / 32, DH / 32, BATCH * HEADS);
        vt_split_kernel<<<gv, 256>>>();
    }
    // 2) Block-sparse causal attention (HMMA) -> g_a_hi/g_a_lo
    {
        dim3 grid(NBLK, HEADS, BATCH);
        sparse_attn_kernel<<<grid, 128, SM_ATT>>>(layout);
    }
    // 3) Output projection (HMMA) + bias -> out
    {
        dim3 grid(DIM / 128, (BATCH * SEQ) / 128);
        tc_gemm2_kernel<<<grid, 256, SM_GEMM>>>(b_out, out);
    }
}